// round 7
// baseline (speedup 1.0000x reference)
#include <cuda_runtime.h>
#include <cuda_bf16.h>
#include <cstdint>

#define BB 16
#define LQ 2048
#define LK 2048
#define DD 512
#define TOPK 512

// ---------------------------------------------------------------------------
// Device-global scratch (no allocations allowed)
// ---------------------------------------------------------------------------
__device__ float         g_scores[(size_t)BB * LQ * LK];                 // 268 MB
__device__ __nv_bfloat16 g_Qh[(size_t)BB * LQ * DD];
__device__ __nv_bfloat16 g_Ql[(size_t)BB * LQ * DD];
__device__ __nv_bfloat16 g_Kh[(size_t)BB * LK * DD];
__device__ __nv_bfloat16 g_Kl[(size_t)BB * LK * DD];
__device__ __nv_bfloat16 g_Vth[(size_t)BB * DD * LK];                    // V^T [b,d,k]
__device__ __nv_bfloat16 g_Vtl[(size_t)BB * DD * LK];
__device__ __nv_bfloat16 g_Ph[(size_t)BB * LQ * LK];
__device__ __nv_bfloat16 g_Pl[(size_t)BB * LQ * LK];

// ---------------------------------------------------------------------------
// PTX helpers (baseline compute_103-safe: cp.async + ldmatrix + mma.sync only)
// ---------------------------------------------------------------------------
__device__ __forceinline__ uint32_t smem_u32(const void* p) {
    uint32_t a;
    asm("{ .reg .u64 t; cvta.to.shared.u64 t, %1; cvt.u32.u64 %0, t; }" : "=r"(a) : "l"(p));
    return a;
}
__device__ __forceinline__ void cp16(uint32_t s, const void* g) {
    asm volatile("cp.async.cg.shared.global [%0], [%1], 16;" :: "r"(s), "l"(g));
}
__device__ __forceinline__ void cp_commit() { asm volatile("cp.async.commit_group;" ::: "memory"); }
__device__ __forceinline__ void cp_wait0()  { asm volatile("cp.async.wait_group 0;" ::: "memory"); }
__device__ __forceinline__ void cp_wait1()  { asm volatile("cp.async.wait_group 1;" ::: "memory"); }

__device__ __forceinline__ void ldsm4(uint32_t* r, uint32_t addr) {
    asm volatile("ldmatrix.sync.aligned.m8n8.x4.shared.b16 {%0,%1,%2,%3}, [%4];"
                 : "=r"(r[0]), "=r"(r[1]), "=r"(r[2]), "=r"(r[3]) : "r"(addr));
}
__device__ __forceinline__ void mma_bf16(float* c, const uint32_t* a, const uint32_t* b) {
    asm volatile("mma.sync.aligned.m16n8k16.row.col.f32.bf16.bf16.f32 "
                 "{%0,%1,%2,%3}, {%4,%5,%6,%7}, {%8,%9}, {%0,%1,%2,%3};"
                 : "+f"(c[0]), "+f"(c[1]), "+f"(c[2]), "+f"(c[3])
                 : "r"(a[0]), "r"(a[1]), "r"(a[2]), "r"(a[3]), "r"(b[0]), "r"(b[1]));
}

// ---------------------------------------------------------------------------
// HMMA GEMM: C[b,m,n] = sum_k (Ah+Al)[m,k] * (Bh+Bl)[n,k]
// TERMS=3: Ah*Bh + Ah*Bl + Al*Bh.  TERMS=4: + Al*Bl (fp32-class accuracy).
// Block tile 128x128, BK=32, 16 warps (warp tile 32x32), cp.async dbl buffer.
// ---------------------------------------------------------------------------
#define MAT_BYTES 8192
#define BUF_BYTES (4 * MAT_BYTES)       // 32 KB
#define GEMM_SMEM (2 * BUF_BYTES)       // 64 KB

__device__ __forceinline__ void load_buf(uint32_t sbase,
    const __nv_bfloat16* __restrict__ Ah, const __nv_bfloat16* __restrict__ Al, long ldA,
    const __nv_bfloat16* __restrict__ Bh, const __nv_bfloat16* __restrict__ Bl, long ldB,
    int kk, int tid)
{
    const int r = tid >> 2;             // 0..127
    const int c = tid & 3;              // 16B chunk within 64B row
    const uint32_t soff = r * 64 + ((c ^ ((r >> 1) & 3)) << 4);
    const size_t goffA = (size_t)r * ldA + kk + c * 8;
    const size_t goffB = (size_t)r * ldB + kk + c * 8;
    cp16(sbase + soff,                 Ah + goffA);
    cp16(sbase + MAT_BYTES + soff,     Al + goffA);
    cp16(sbase + 2 * MAT_BYTES + soff, Bh + goffB);
    cp16(sbase + 3 * MAT_BYTES + soff, Bl + goffB);
}

template <int TERMS>
__global__ __launch_bounds__(512, 1)
void hmma_gemm(const __nv_bfloat16* __restrict__ Ah, const __nv_bfloat16* __restrict__ Al,
               long ldA, long strideA,
               const __nv_bfloat16* __restrict__ Bh, const __nv_bfloat16* __restrict__ Bl,
               long ldB, long strideB,
               float* __restrict__ C, long ldC, long strideC, int Ktot)
{
    extern __shared__ char smem[];
    const uint32_t sbase = smem_u32(smem);

    const int tid  = threadIdx.x;
    const int lane = tid & 31, warp = tid >> 5;
    const int wm = (warp >> 2) * 32;      // 4 m-groups of 32 rows
    const int wn = (warp & 3) * 32;       // 4 n-groups of 32 cols
    const int b  = blockIdx.z;
    const int n0 = blockIdx.x * 128, m0 = blockIdx.y * 128;

    const __nv_bfloat16* pAh = Ah + (size_t)b * strideA + (size_t)m0 * ldA;
    const __nv_bfloat16* pAl = Al + (size_t)b * strideA + (size_t)m0 * ldA;
    const __nv_bfloat16* pBh = Bh + (size_t)b * strideB + (size_t)n0 * ldB;
    const __nv_bfloat16* pBl = Bl + (size_t)b * strideB + (size_t)n0 * ldB;

    const int aRow = (lane & 7) | (((lane >> 3) & 1) << 3);
    const int aCk  = (lane >> 4) & 1;
    const int bRow = (lane & 7) | (((lane >> 4) & 1) << 3);
    const int bCk  = (lane >> 3) & 1;

    float acc[2][4][4];
#pragma unroll
    for (int i = 0; i < 2; i++)
#pragma unroll
        for (int j = 0; j < 4; j++)
#pragma unroll
            for (int t = 0; t < 4; t++) acc[i][j][t] = 0.f;

    const int nc = Ktot / 32;

    load_buf(sbase, pAh, pAl, ldA, pBh, pBl, ldB, 0, tid);
    cp_commit();

    for (int c = 0; c < nc; c++) {
        if (c + 1 < nc) {
            load_buf(sbase + ((c + 1) & 1) * BUF_BYTES, pAh, pAl, ldA, pBh, pBl, ldB,
                     (c + 1) * 32, tid);
            cp_commit();
            cp_wait1();
        } else {
            cp_wait0();
        }
        __syncthreads();

        const uint32_t bb = sbase + (c & 1) * BUF_BYTES;
#pragma unroll
        for (int s = 0; s < 2; s++) {
            uint32_t ah[2][4], al[2][4], bh[2][4], bl[2][4];
#pragma unroll
            for (int mi = 0; mi < 2; mi++) {
                const int r = wm + mi * 16 + aRow;
                const int ck = s * 2 + aCk;
                const uint32_t off = r * 64 + ((ck ^ ((r >> 1) & 3)) << 4);
                ldsm4(ah[mi], bb + off);
                ldsm4(al[mi], bb + MAT_BYTES + off);
            }
#pragma unroll
            for (int np = 0; np < 2; np++) {
                const int r = wn + np * 16 + bRow;
                const int ck = s * 2 + bCk;
                const uint32_t off = r * 64 + ((ck ^ ((r >> 1) & 3)) << 4);
                ldsm4(bh[np], bb + 2 * MAT_BYTES + off);
                ldsm4(bl[np], bb + 3 * MAT_BYTES + off);
            }
#pragma unroll
            for (int mi = 0; mi < 2; mi++)
#pragma unroll
                for (int nj = 0; nj < 4; nj++)
                    mma_bf16(acc[mi][nj], ah[mi], &bh[nj >> 1][(nj & 1) * 2]);
#pragma unroll
            for (int mi = 0; mi < 2; mi++)
#pragma unroll
                for (int nj = 0; nj < 4; nj++)
                    mma_bf16(acc[mi][nj], ah[mi], &bl[nj >> 1][(nj & 1) * 2]);
#pragma unroll
            for (int mi = 0; mi < 2; mi++)
#pragma unroll
                for (int nj = 0; nj < 4; nj++)
                    mma_bf16(acc[mi][nj], al[mi], &bh[nj >> 1][(nj & 1) * 2]);
            if (TERMS == 4) {
#pragma unroll
                for (int mi = 0; mi < 2; mi++)
#pragma unroll
                    for (int nj = 0; nj < 4; nj++)
                        mma_bf16(acc[mi][nj], al[mi], &bl[nj >> 1][(nj & 1) * 2]);
            }
        }
        __syncthreads();
    }

    const int g = lane >> 2, tg = lane & 3;
    float* Cb = C + (size_t)b * strideC;
#pragma unroll
    for (int mi = 0; mi < 2; mi++) {
        const int row = m0 + wm + mi * 16 + g;
#pragma unroll
        for (int nj = 0; nj < 4; nj++) {
            const int col = n0 + wn + nj * 8 + tg * 2;
            *(float2*)(Cb + (size_t)row * ldC + col)       = make_float2(acc[mi][nj][0], acc[mi][nj][1]);
            *(float2*)(Cb + (size_t)(row + 8) * ldC + col) = make_float2(acc[mi][nj][2], acc[mi][nj][3]);
        }
    }
}

// ---------------------------------------------------------------------------
// fp32 -> (hi, lo) bf16 split, optional scale
// ---------------------------------------------------------------------------
__global__ void split_kernel(const float4* __restrict__ in,
                             __nv_bfloat16* __restrict__ hi,
                             __nv_bfloat16* __restrict__ lo,
                             float scale, int n4)
{
    int i = blockIdx.x * blockDim.x + threadIdx.x;
    if (i >= n4) return;
    float4 v = in[i];
    float x0 = v.x * scale, x1 = v.y * scale, x2 = v.z * scale, x3 = v.w * scale;
    __nv_bfloat16 h0 = __float2bfloat16(x0), h1 = __float2bfloat16(x1);
    __nv_bfloat16 h2 = __float2bfloat16(x2), h3 = __float2bfloat16(x3);
    __nv_bfloat16 l0 = __float2bfloat16(x0 - __bfloat162float(h0));
    __nv_bfloat16 l1 = __float2bfloat16(x1 - __bfloat162float(h1));
    __nv_bfloat16 l2 = __float2bfloat16(x2 - __bfloat162float(h2));
    __nv_bfloat16 l3 = __float2bfloat16(x3 - __bfloat162float(h3));
    uint2 hv, lv;
    hv.x = (uint32_t)__bfloat16_as_ushort(h0) | ((uint32_t)__bfloat16_as_ushort(h1) << 16);
    hv.y = (uint32_t)__bfloat16_as_ushort(h2) | ((uint32_t)__bfloat16_as_ushort(h3) << 16);
    lv.x = (uint32_t)__bfloat16_as_ushort(l0) | ((uint32_t)__bfloat16_as_ushort(l1) << 16);
    lv.y = (uint32_t)__bfloat16_as_ushort(l2) | ((uint32_t)__bfloat16_as_ushort(l3) << 16);
    *(uint2*)(hi + 4 * (size_t)i) = hv;
    *(uint2*)(lo + 4 * (size_t)i) = lv;
}

// ---------------------------------------------------------------------------
// Transpose V [b,k,d] -> Vt [b,d,k], split hi/lo bf16
// ---------------------------------------------------------------------------
__global__ void vt_split(const float* __restrict__ V)
{
    __shared__ float tile[32][33];
    const int b = blockIdx.z;
    const int k0 = blockIdx.x * 32, d0 = blockIdx.y * 32;
    const float* Vb = V + (size_t)b * LK * DD;
#pragma unroll
    for (int i = threadIdx.y; i < 32; i += 8)
        tile[i][threadIdx.x] = Vb[(size_t)(k0 + i) * DD + d0 + threadIdx.x];
    __syncthreads();
#pragma unroll
    for (int i = threadIdx.y; i < 32; i += 8) {
        float x = tile[threadIdx.x][i];
        size_t o = (size_t)b * DD * LK + (size_t)(d0 + i) * LK + k0 + threadIdx.x;
        __nv_bfloat16 h = __float2bfloat16(x);
        g_Vth[o] = h;
        g_Vtl[o] = __float2bfloat16(x - __bfloat162float(h));
    }
}

// ---------------------------------------------------------------------------
// Top-k (exact 512th-largest via MSB radix select) + sparse softmax.
// Warp-shuffle reductions + single-warp suffix scan (few barriers).
// ---------------------------------------------------------------------------
__device__ __forceinline__ unsigned fkey(float x) {
    unsigned u = __float_as_uint(x);
    return u ^ ((u >> 31) ? 0xFFFFFFFFu : 0x80000000u);
}
__device__ __forceinline__ float fkey_inv(unsigned u) {
    unsigned bits = (u >> 31) ? (u ^ 0x80000000u) : ~u;
    return __uint_as_float(bits);
}

__global__ __launch_bounds__(256)
void topk_softmax(void)
{
    __shared__ float row[LK];
    __shared__ unsigned hist[256];
    __shared__ float redf[8];
    __shared__ float s_bcast;
    __shared__ int s_bin, s_k;

    const int tid = threadIdx.x;
    const int lane = tid & 31, wid = tid >> 5;
    const float* Srow = g_scores + (size_t)blockIdx.x * LK;
    __nv_bfloat16* PhR = g_Ph + (size_t)blockIdx.x * LK;
    __nv_bfloat16* PlR = g_Pl + (size_t)blockIdx.x * LK;

    for (int i = tid; i < LK / 4; i += 256)
        ((float4*)row)[i] = ((const float4*)Srow)[i];
    __syncthreads();

    // ---- row max (shfl + 8-slot smem) ----
    float m = -3.4e38f;
    for (int i = tid; i < LK; i += 256) m = fmaxf(m, row[i]);
#pragma unroll
    for (int o = 16; o > 0; o >>= 1) m = fmaxf(m, __shfl_xor_sync(0xFFFFFFFFu, m, o));
    if (lane == 0) redf[wid] = m;
    __syncthreads();
    if (tid == 0) {
        float mm = redf[0];
#pragma unroll
        for (int i = 1; i < 8; i++) mm = fmaxf(mm, redf[i]);
        s_bcast = mm;
    }
    __syncthreads();
    const float rowmax = s_bcast;

    // ---- MSB-first radix select of 512th-largest ----
    unsigned prefix = 0;
    int k = TOPK;
#pragma unroll
    for (int pass = 0; pass < 4; pass++) {
        const int shift = 24 - pass * 8;
        if (tid < 256) hist[tid] = 0;
        __syncthreads();
        const unsigned mask = pass ? (0xFFFFFFFFu << (32 - 8 * pass)) : 0u;
        for (int i = tid; i < LK; i += 256) {
            unsigned u = fkey(row[i]);
            if ((u & mask) == prefix)
                atomicAdd(&hist[(u >> shift) & 0xFF], 1u);
        }
        __syncthreads();
        if (wid == 0) {
            // lane handles 8 consecutive bins
            unsigned h[8], tot = 0;
#pragma unroll
            for (int j = 0; j < 8; j++) { h[j] = hist[lane * 8 + j]; tot += h[j]; }
            // inclusive suffix across lanes
            unsigned suf = tot;
#pragma unroll
            for (int o = 1; o < 32; o <<= 1) {
                unsigned v = __shfl_down_sync(0xFFFFFFFFu, suf, o);
                if (lane + o < 32) suf += v;
            }
            unsigned run = suf - tot;   // count in bins strictly above this lane's range
            for (int j = 7; j >= 0; j--) {
                unsigned cge = run + h[j];
                if (cge >= (unsigned)k && run < (unsigned)k) {
                    s_bin = lane * 8 + j;
                    s_k = k - (int)run;
                }
                run = cge;
            }
        }
        __syncthreads();
        prefix |= ((unsigned)s_bin << shift);
        k = s_k;
        __syncthreads();
    }
    const float tau = fkey_inv(prefix);

    // ---- sum of exp over selected ----
    float ssum = 0.f;
    for (int i = tid; i < LK; i += 256) {
        float x = row[i];
        if (x >= tau) ssum += __expf(x - rowmax);
    }
#pragma unroll
    for (int o = 16; o > 0; o >>= 1) ssum += __shfl_xor_sync(0xFFFFFFFFu, ssum, o);
    if (lane == 0) redf[wid] = ssum;
    __syncthreads();
    if (tid == 0) {
        float t = 0.f;
#pragma unroll
        for (int i = 0; i < 8; i++) t += redf[i];
        s_bcast = 1.0f / t;
    }
    __syncthreads();
    const float inv = s_bcast;

    for (int i = tid; i < LK; i += 256) {
        float x = row[i];
        float p = (x >= tau) ? __expf(x - rowmax) * inv : 0.f;
        __nv_bfloat16 h = __float2bfloat16(p);
        PhR[i] = h;
        PlR[i] = __float2bfloat16(p - __bfloat162float(h));
    }
}

// ---------------------------------------------------------------------------
extern "C" void kernel_launch(void* const* d_in, const int* in_sizes, int n_in,
                              void* d_out, int out_size)
{
    const float* Q = (const float*)d_in[0];
    const float* K = (const float*)d_in[1];
    const float* V = (const float*)d_in[2];
    float* O = (float*)d_out;

    cudaFuncSetAttribute(hmma_gemm<4>, cudaFuncAttributeMaxDynamicSharedMemorySize, GEMM_SMEM);
    cudaFuncSetAttribute(hmma_gemm<3>, cudaFuncAttributeMaxDynamicSharedMemorySize, GEMM_SMEM);

    void *pQh, *pQl, *pKh, *pKl, *pVth, *pVtl, *pPh, *pPl, *pS;
    cudaGetSymbolAddress(&pQh, g_Qh);   cudaGetSymbolAddress(&pQl, g_Ql);
    cudaGetSymbolAddress(&pKh, g_Kh);   cudaGetSymbolAddress(&pKl, g_Kl);
    cudaGetSymbolAddress(&pVth, g_Vth); cudaGetSymbolAddress(&pVtl, g_Vtl);
    cudaGetSymbolAddress(&pPh, g_Ph);   cudaGetSymbolAddress(&pPl, g_Pl);
    cudaGetSymbolAddress(&pS, g_scores);

    const float scale = 0.04419417382415922f;   // 1/sqrt(512)
    const int n4 = (BB * LQ * DD) / 4;

    split_kernel<<<(n4 + 255) / 256, 256>>>((const float4*)Q,
        (__nv_bfloat16*)pQh, (__nv_bfloat16*)pQl, scale, n4);
    split_kernel<<<(n4 + 255) / 256, 256>>>((const float4*)K,
        (__nv_bfloat16*)pKh, (__nv_bfloat16*)pKl, 1.0f, n4);

    dim3 tb(32, 8), tg(LK / 32, DD / 32, BB);
    vt_split<<<tg, tb>>>(V);

    // scores = (Q*scale) @ K^T  — 4-term split: fp32-class accuracy for selection
    hmma_gemm<4><<<dim3(LK / 128, LQ / 128, BB), 512, GEMM_SMEM>>>(
        (const __nv_bfloat16*)pQh, (const __nv_bfloat16*)pQl, DD, (long)LQ * DD,
        (const __nv_bfloat16*)pKh, (const __nv_bfloat16*)pKl, DD, (long)LK * DD,
        (float*)pS, LK, (long)LQ * LK, DD);

    topk_softmax<<<BB * LQ, 256>>>();

    // O = P @ V   (V pre-transposed to [b,d,k]) — 3-term suffices
    hmma_gemm<3><<<dim3(DD / 128, LQ / 128, BB), 512, GEMM_SMEM>>>(
        (const __nv_bfloat16*)pPh, (const __nv_bfloat16*)pPl, LK, (long)LQ * LK,
        (const __nv_bfloat16*)pVth, (const __nv_bfloat16*)pVtl, LK, (long)DD * LK,
        O, DD, (long)LQ * DD, LK);
}

// round 8
// speedup vs baseline: 1.1579x; 1.1579x over previous
#include <cuda_runtime.h>
#include <cuda_bf16.h>
#include <cstdint>

#define BB 16
#define LQ 2048
#define LK 2048
#define DD 512
#define TOPK 512

// ---------------------------------------------------------------------------
// Device-global scratch (no allocations allowed)
// ---------------------------------------------------------------------------
__device__ float         g_scores[(size_t)BB * LQ * LK];                 // 268 MB
__device__ __nv_bfloat16 g_Qh[(size_t)BB * LQ * DD];
__device__ __nv_bfloat16 g_Ql[(size_t)BB * LQ * DD];
__device__ __nv_bfloat16 g_Kh[(size_t)BB * LK * DD];
__device__ __nv_bfloat16 g_Kl[(size_t)BB * LK * DD];
__device__ __nv_bfloat16 g_Vth[(size_t)BB * DD * LK];                    // V^T [b,d,k]
__device__ __nv_bfloat16 g_Vtl[(size_t)BB * DD * LK];
__device__ __nv_bfloat16 g_Ph[(size_t)BB * LQ * LK];
__device__ __nv_bfloat16 g_Pl[(size_t)BB * LQ * LK];

// ---------------------------------------------------------------------------
// PTX helpers
// ---------------------------------------------------------------------------
__device__ __forceinline__ uint32_t smem_u32(const void* p) {
    uint32_t a;
    asm("{ .reg .u64 t; cvta.to.shared.u64 t, %1; cvt.u32.u64 %0, t; }" : "=r"(a) : "l"(p));
    return a;
}
__device__ __forceinline__ void cp16(uint32_t s, const void* g) {
    asm volatile("cp.async.cg.shared.global [%0], [%1], 16;" :: "r"(s), "l"(g));
}
__device__ __forceinline__ void cp_commit() { asm volatile("cp.async.commit_group;" ::: "memory"); }
__device__ __forceinline__ void cp_wait0()  { asm volatile("cp.async.wait_group 0;" ::: "memory"); }
__device__ __forceinline__ void cp_wait1()  { asm volatile("cp.async.wait_group 1;" ::: "memory"); }

__device__ __forceinline__ void ldsm4(uint32_t* r, uint32_t addr) {
    asm volatile("ldmatrix.sync.aligned.m8n8.x4.shared.b16 {%0,%1,%2,%3}, [%4];"
                 : "=r"(r[0]), "=r"(r[1]), "=r"(r[2]), "=r"(r[3]) : "r"(addr));
}
__device__ __forceinline__ void mma_bf16(float* c, const uint32_t* a, const uint32_t* b) {
    asm volatile("mma.sync.aligned.m16n8k16.row.col.f32.bf16.bf16.f32 "
                 "{%0,%1,%2,%3}, {%4,%5,%6,%7}, {%8,%9}, {%0,%1,%2,%3};"
                 : "+f"(c[0]), "+f"(c[1]), "+f"(c[2]), "+f"(c[3])
                 : "r"(a[0]), "r"(a[1]), "r"(a[2]), "r"(a[3]), "r"(b[0]), "r"(b[1]));
}

// ---------------------------------------------------------------------------
// HMMA GEMM: C[b,m,n] = sum_k (Ah+Al)[m,k] * (Bh+Bl)[n,k]
// TERMS=3: hh+hl+lh.  TERMS=4: +ll.
// Block tile 128x128, BK=32, 8 warps (warp tile 64x32), 2 CTAs/SM.
// A-fragments loaded per 32-row half to keep regs <= 128.
// ---------------------------------------------------------------------------
#define MAT_BYTES 8192
#define BUF_BYTES (4 * MAT_BYTES)       // 32 KB
#define GEMM_SMEM (2 * BUF_BYTES)       // 64 KB

__device__ __forceinline__ void load_buf(uint32_t sbase,
    const __nv_bfloat16* __restrict__ Ah, const __nv_bfloat16* __restrict__ Al, long ldA,
    const __nv_bfloat16* __restrict__ Bh, const __nv_bfloat16* __restrict__ Bl, long ldB,
    int kk, int tid)
{
    const int r0 = tid >> 2;            // 0..63
    const int c  = tid & 3;
#pragma unroll
    for (int p = 0; p < 2; p++) {
        const int r = r0 + p * 64;
        const uint32_t soff = r * 64 + ((c ^ ((r >> 1) & 3)) << 4);
        const size_t goffA = (size_t)r * ldA + kk + c * 8;
        const size_t goffB = (size_t)r * ldB + kk + c * 8;
        cp16(sbase + soff,                 Ah + goffA);
        cp16(sbase + MAT_BYTES + soff,     Al + goffA);
        cp16(sbase + 2 * MAT_BYTES + soff, Bh + goffB);
        cp16(sbase + 3 * MAT_BYTES + soff, Bl + goffB);
    }
}

template <int TERMS>
__global__ __launch_bounds__(256, 2)
void hmma_gemm(const __nv_bfloat16* __restrict__ Ah, const __nv_bfloat16* __restrict__ Al,
               long ldA, long strideA,
               const __nv_bfloat16* __restrict__ Bh, const __nv_bfloat16* __restrict__ Bl,
               long ldB, long strideB,
               float* __restrict__ C, long ldC, long strideC, int Ktot)
{
    extern __shared__ char smem[];
    const uint32_t sbase = smem_u32(smem);

    const int tid  = threadIdx.x;
    const int lane = tid & 31, warp = tid >> 5;
    const int wm = (warp >> 2) * 64;      // 2 m-groups of 64 rows
    const int wn = (warp & 3) * 32;       // 4 n-groups of 32 cols
    const int b  = blockIdx.z;
    const int n0 = blockIdx.x * 128, m0 = blockIdx.y * 128;

    const __nv_bfloat16* pAh = Ah + (size_t)b * strideA + (size_t)m0 * ldA;
    const __nv_bfloat16* pAl = Al + (size_t)b * strideA + (size_t)m0 * ldA;
    const __nv_bfloat16* pBh = Bh + (size_t)b * strideB + (size_t)n0 * ldB;
    const __nv_bfloat16* pBl = Bl + (size_t)b * strideB + (size_t)n0 * ldB;

    const int aRow = (lane & 7) | (((lane >> 3) & 1) << 3);
    const int aCk  = (lane >> 4) & 1;
    const int bRow = (lane & 7) | (((lane >> 4) & 1) << 3);
    const int bCk  = (lane >> 3) & 1;

    float acc[4][4][4];
#pragma unroll
    for (int i = 0; i < 4; i++)
#pragma unroll
        for (int j = 0; j < 4; j++)
#pragma unroll
            for (int t = 0; t < 4; t++) acc[i][j][t] = 0.f;

    const int nc = Ktot / 32;

    load_buf(sbase, pAh, pAl, ldA, pBh, pBl, ldB, 0, tid);
    cp_commit();

    for (int c = 0; c < nc; c++) {
        if (c + 1 < nc) {
            load_buf(sbase + ((c + 1) & 1) * BUF_BYTES, pAh, pAl, ldA, pBh, pBl, ldB,
                     (c + 1) * 32, tid);
            cp_commit();
            cp_wait1();
        } else {
            cp_wait0();
        }
        __syncthreads();

        const uint32_t bb = sbase + (c & 1) * BUF_BYTES;
#pragma unroll
        for (int s = 0; s < 2; s++) {
            uint32_t bh[2][4], bl[2][4];
#pragma unroll
            for (int np = 0; np < 2; np++) {
                const int r = wn + np * 16 + bRow;
                const int ck = s * 2 + bCk;
                const uint32_t off = r * 64 + ((ck ^ ((r >> 1) & 3)) << 4);
                ldsm4(bh[np], bb + 2 * MAT_BYTES + off);
                ldsm4(bl[np], bb + 3 * MAT_BYTES + off);
            }
#pragma unroll
            for (int mh = 0; mh < 2; mh++) {
                uint32_t ah[2][4], al[2][4];
#pragma unroll
                for (int mi = 0; mi < 2; mi++) {
                    const int r = wm + mh * 32 + mi * 16 + aRow;
                    const int ck = s * 2 + aCk;
                    const uint32_t off = r * 64 + ((ck ^ ((r >> 1) & 3)) << 4);
                    ldsm4(ah[mi], bb + off);
                    ldsm4(al[mi], bb + MAT_BYTES + off);
                }
#pragma unroll
                for (int mi = 0; mi < 2; mi++)
#pragma unroll
                    for (int nj = 0; nj < 4; nj++)
                        mma_bf16(acc[mh * 2 + mi][nj], ah[mi], &bh[nj >> 1][(nj & 1) * 2]);
#pragma unroll
                for (int mi = 0; mi < 2; mi++)
#pragma unroll
                    for (int nj = 0; nj < 4; nj++)
                        mma_bf16(acc[mh * 2 + mi][nj], ah[mi], &bl[nj >> 1][(nj & 1) * 2]);
#pragma unroll
                for (int mi = 0; mi < 2; mi++)
#pragma unroll
                    for (int nj = 0; nj < 4; nj++)
                        mma_bf16(acc[mh * 2 + mi][nj], al[mi], &bh[nj >> 1][(nj & 1) * 2]);
                if (TERMS == 4) {
#pragma unroll
                    for (int mi = 0; mi < 2; mi++)
#pragma unroll
                        for (int nj = 0; nj < 4; nj++)
                            mma_bf16(acc[mh * 2 + mi][nj], al[mi], &bl[nj >> 1][(nj & 1) * 2]);
                }
            }
        }
        __syncthreads();
    }

    const int g = lane >> 2, tg = lane & 3;
    float* Cb = C + (size_t)b * strideC;
#pragma unroll
    for (int mi = 0; mi < 4; mi++) {
        const int row = m0 + wm + mi * 16 + g;
#pragma unroll
        for (int nj = 0; nj < 4; nj++) {
            const int col = n0 + wn + nj * 8 + tg * 2;
            *(float2*)(Cb + (size_t)row * ldC + col)       = make_float2(acc[mi][nj][0], acc[mi][nj][1]);
            *(float2*)(Cb + (size_t)(row + 8) * ldC + col) = make_float2(acc[mi][nj][2], acc[mi][nj][3]);
        }
    }
}

// ---------------------------------------------------------------------------
// fp32 -> (hi, lo) bf16 split, optional scale
// ---------------------------------------------------------------------------
__global__ void split_kernel(const float4* __restrict__ in,
                             __nv_bfloat16* __restrict__ hi,
                             __nv_bfloat16* __restrict__ lo,
                             float scale, int n4)
{
    int i = blockIdx.x * blockDim.x + threadIdx.x;
    if (i >= n4) return;
    float4 v = in[i];
    float x0 = v.x * scale, x1 = v.y * scale, x2 = v.z * scale, x3 = v.w * scale;
    __nv_bfloat16 h0 = __float2bfloat16(x0), h1 = __float2bfloat16(x1);
    __nv_bfloat16 h2 = __float2bfloat16(x2), h3 = __float2bfloat16(x3);
    __nv_bfloat16 l0 = __float2bfloat16(x0 - __bfloat162float(h0));
    __nv_bfloat16 l1 = __float2bfloat16(x1 - __bfloat162float(h1));
    __nv_bfloat16 l2 = __float2bfloat16(x2 - __bfloat162float(h2));
    __nv_bfloat16 l3 = __float2bfloat16(x3 - __bfloat162float(h3));
    uint2 hv, lv;
    hv.x = (uint32_t)__bfloat16_as_ushort(h0) | ((uint32_t)__bfloat16_as_ushort(h1) << 16);
    hv.y = (uint32_t)__bfloat16_as_ushort(h2) | ((uint32_t)__bfloat16_as_ushort(h3) << 16);
    lv.x = (uint32_t)__bfloat16_as_ushort(l0) | ((uint32_t)__bfloat16_as_ushort(l1) << 16);
    lv.y = (uint32_t)__bfloat16_as_ushort(l2) | ((uint32_t)__bfloat16_as_ushort(l3) << 16);
    *(uint2*)(hi + 4 * (size_t)i) = hv;
    *(uint2*)(lo + 4 * (size_t)i) = lv;
}

// ---------------------------------------------------------------------------
// Transpose V [b,k,d] -> Vt [b,d,k], split hi/lo bf16
// ---------------------------------------------------------------------------
__global__ void vt_split(const float* __restrict__ V)
{
    __shared__ float tile[32][33];
    const int b = blockIdx.z;
    const int k0 = blockIdx.x * 32, d0 = blockIdx.y * 32;
    const float* Vb = V + (size_t)b * LK * DD;
#pragma unroll
    for (int i = threadIdx.y; i < 32; i += 8)
        tile[i][threadIdx.x] = Vb[(size_t)(k0 + i) * DD + d0 + threadIdx.x];
    __syncthreads();
#pragma unroll
    for (int i = threadIdx.y; i < 32; i += 8) {
        float x = tile[threadIdx.x][i];
        size_t o = (size_t)b * DD * LK + (size_t)(d0 + i) * LK + k0 + threadIdx.x;
        __nv_bfloat16 h = __float2bfloat16(x);
        g_Vth[o] = h;
        g_Vtl[o] = __float2bfloat16(x - __bfloat162float(h));
    }
}

// ---------------------------------------------------------------------------
// Top-k (exact 512th-largest via MSB radix select with candidate compaction)
// + sparse softmax. Writes Ph/Pl bf16 hi/lo directly.
// ---------------------------------------------------------------------------
__device__ __forceinline__ unsigned fkey(float x) {
    unsigned u = __float_as_uint(x);
    return u ^ ((u >> 31) ? 0xFFFFFFFFu : 0x80000000u);
}
__device__ __forceinline__ float fkey_inv(unsigned u) {
    unsigned bits = (u >> 31) ? (u ^ 0x80000000u) : ~u;
    return __uint_as_float(bits);
}

#define CAND_CAP 1024

__global__ __launch_bounds__(256)
void topk_softmax(void)
{
    __shared__ float row[LK];            // 8 KB
    __shared__ float cand[CAND_CAP];     // 4 KB
    __shared__ unsigned hist[256];
    __shared__ float redf[8];
    __shared__ float s_bcast;
    __shared__ int s_bin, s_k, s_cnt;

    const int tid = threadIdx.x;
    const int lane = tid & 31, wid = tid >> 5;
    const float* Srow = g_scores + (size_t)blockIdx.x * LK;
    __nv_bfloat16* PhR = g_Ph + (size_t)blockIdx.x * LK;
    __nv_bfloat16* PlR = g_Pl + (size_t)blockIdx.x * LK;

    if (tid < 256) hist[tid] = 0;
    if (tid == 0) s_cnt = 0;
    __syncthreads();

    // ---- load + rowmax + pass-0 histogram (bits 31:24), one scan ----
    float m = -3.4e38f;
    for (int i = tid; i < LK / 4; i += 256) {
        float4 v = ((const float4*)Srow)[i];
        ((float4*)row)[i] = v;
        m = fmaxf(fmaxf(m, v.x), fmaxf(v.y, v.z));
        m = fmaxf(m, v.w);
        atomicAdd(&hist[fkey(v.x) >> 24], 1u);
        atomicAdd(&hist[fkey(v.y) >> 24], 1u);
        atomicAdd(&hist[fkey(v.z) >> 24], 1u);
        atomicAdd(&hist[fkey(v.w) >> 24], 1u);
    }
#pragma unroll
    for (int o = 16; o > 0; o >>= 1) m = fmaxf(m, __shfl_xor_sync(0xFFFFFFFFu, m, o));
    if (lane == 0) redf[wid] = m;
    __syncthreads();
    if (tid == 0) {
        float mm = redf[0];
#pragma unroll
        for (int i = 1; i < 8; i++) mm = fmaxf(mm, redf[i]);
        s_bcast = mm;
    }

    unsigned prefix = 0;
    int k = TOPK;

    // bin selection from hist (warp 0): inclusive suffix scan over 256 bins
#define SELECT_BIN()                                                            \
    do {                                                                        \
        if (wid == 0) {                                                         \
            unsigned h[8], tot = 0;                                             \
            for (int j = 0; j < 8; j++) { h[j] = hist[lane * 8 + j]; tot += h[j]; } \
            unsigned suf = tot;                                                 \
            for (int o = 1; o < 32; o <<= 1) {                                  \
                unsigned v = __shfl_down_sync(0xFFFFFFFFu, suf, o);             \
                if (lane + o < 32) suf += v;                                    \
            }                                                                   \
            unsigned run = suf - tot;                                           \
            for (int j = 7; j >= 0; j--) {                                      \
                unsigned cge = run + h[j];                                      \
                if (cge >= (unsigned)k && run < (unsigned)k) {                  \
                    s_bin = lane * 8 + j;                                       \
                    s_k = k - (int)run;                                         \
                }                                                               \
                run = cge;                                                      \
            }                                                                   \
        }                                                                       \
    } while (0)

    __syncthreads();
    SELECT_BIN();
    __syncthreads();
    prefix = (unsigned)s_bin << 24;
    k = s_k;
    const float rowmax = s_bcast;
    __syncthreads();

    // ---- pass 1 (bits 23:16): scan full row, compact candidates ----
    if (tid < 256) hist[tid] = 0;
    __syncthreads();
    for (int i = tid; i < LK; i += 256) {
        float x = row[i];
        unsigned u = fkey(x);
        if ((u >> 24) == (prefix >> 24)) {
            int idx = atomicAdd(&s_cnt, 1);
            if (idx < CAND_CAP) cand[idx] = x;
            atomicAdd(&hist[(u >> 16) & 0xFF], 1u);
        }
    }
    __syncthreads();
    SELECT_BIN();
    __syncthreads();
    prefix |= (unsigned)s_bin << 16;
    k = s_k;
    const int ncand = s_cnt;
    const bool uselist = (ncand <= CAND_CAP);
    __syncthreads();

    // ---- passes 2,3 over candidate list (or full row on overflow) ----
#pragma unroll
    for (int pass = 2; pass < 4; pass++) {
        const int shift = 24 - pass * 8;
        const unsigned mask = 0xFFFFFFFFu << (32 - 8 * pass);
        if (tid < 256) hist[tid] = 0;
        __syncthreads();
        if (uselist) {
            for (int i = tid; i < ncand; i += 256) {
                unsigned u = fkey(cand[i]);
                if ((u & mask) == prefix)
                    atomicAdd(&hist[(u >> shift) & 0xFF], 1u);
            }
        } else {
            for (int i = tid; i < LK; i += 256) {
                unsigned u = fkey(row[i]);
                if ((u & mask) == prefix)
                    atomicAdd(&hist[(u >> shift) & 0xFF], 1u);
            }
        }
        __syncthreads();
        SELECT_BIN();
        __syncthreads();
        prefix |= (unsigned)s_bin << shift;
        k = s_k;
        __syncthreads();
    }
    const float tau = fkey_inv(prefix);

    // ---- sum of exp over selected ----
    float ssum = 0.f;
    for (int i = tid; i < LK; i += 256) {
        float x = row[i];
        if (x >= tau) ssum += __expf(x - rowmax);
    }
#pragma unroll
    for (int o = 16; o > 0; o >>= 1) ssum += __shfl_xor_sync(0xFFFFFFFFu, ssum, o);
    if (lane == 0) redf[wid] = ssum;
    __syncthreads();
    if (tid == 0) {
        float t = 0.f;
#pragma unroll
        for (int i = 0; i < 8; i++) t += redf[i];
        s_bcast = 1.0f / t;
    }
    __syncthreads();
    const float inv = s_bcast;

    for (int i = tid; i < LK; i += 256) {
        float x = row[i];
        float p = (x >= tau) ? __expf(x - rowmax) * inv : 0.f;
        __nv_bfloat16 h = __float2bfloat16(p);
        PhR[i] = h;
        PlR[i] = __float2bfloat16(p - __bfloat162float(h));
    }
#undef SELECT_BIN
}

// ---------------------------------------------------------------------------
extern "C" void kernel_launch(void* const* d_in, const int* in_sizes, int n_in,
                              void* d_out, int out_size)
{
    const float* Q = (const float*)d_in[0];
    const float* K = (const float*)d_in[1];
    const float* V = (const float*)d_in[2];
    float* O = (float*)d_out;

    cudaFuncSetAttribute(hmma_gemm<4>, cudaFuncAttributeMaxDynamicSharedMemorySize, GEMM_SMEM);
    cudaFuncSetAttribute(hmma_gemm<3>, cudaFuncAttributeMaxDynamicSharedMemorySize, GEMM_SMEM);

    void *pQh, *pQl, *pKh, *pKl, *pVth, *pVtl, *pPh, *pPl, *pS;
    cudaGetSymbolAddress(&pQh, g_Qh);   cudaGetSymbolAddress(&pQl, g_Ql);
    cudaGetSymbolAddress(&pKh, g_Kh);   cudaGetSymbolAddress(&pKl, g_Kl);
    cudaGetSymbolAddress(&pVth, g_Vth); cudaGetSymbolAddress(&pVtl, g_Vtl);
    cudaGetSymbolAddress(&pPh, g_Ph);   cudaGetSymbolAddress(&pPl, g_Pl);
    cudaGetSymbolAddress(&pS, g_scores);

    const float scale = 0.04419417382415922f;   // 1/sqrt(512)
    const int n4 = (BB * LQ * DD) / 4;

    split_kernel<<<(n4 + 255) / 256, 256>>>((const float4*)Q,
        (__nv_bfloat16*)pQh, (__nv_bfloat16*)pQl, scale, n4);
    split_kernel<<<(n4 + 255) / 256, 256>>>((const float4*)K,
        (__nv_bfloat16*)pKh, (__nv_bfloat16*)pKl, 1.0f, n4);

    dim3 tb(32, 8), tg(LK / 32, DD / 32, BB);
    vt_split<<<tg, tb>>>(V);

    // scores = (Q*scale) @ K^T  — 4-term split
    hmma_gemm<4><<<dim3(LK / 128, LQ / 128, BB), 256, GEMM_SMEM>>>(
        (const __nv_bfloat16*)pQh, (const __nv_bfloat16*)pQl, DD, (long)LQ * DD,
        (const __nv_bfloat16*)pKh, (const __nv_bfloat16*)pKl, DD, (long)LK * DD,
        (float*)pS, LK, (long)LQ * LK, DD);

    topk_softmax<<<BB * LQ, 256>>>();

    // O = P @ V   (V pre-transposed to [b,d,k]) — 3-term
    hmma_gemm<3><<<dim3(DD / 128, LQ / 128, BB), 256, GEMM_SMEM>>>(
        (const __nv_bfloat16*)pPh, (const __nv_bfloat16*)pPl, LK, (long)LQ * LK,
        (const __nv_bfloat16*)pVth, (const __nv_bfloat16*)pVtl, LK, (long)DD * LK,
        O, DD, (long)LQ * DD, LK);
}

// round 9
// speedup vs baseline: 1.2507x; 1.0802x over previous
#include <cuda_runtime.h>
#include <cuda_fp16.h>
#include <cstdint>

#define BB 16
#define LQ 2048
#define LK 2048
#define DD 512
#define TOPK 512

// ---------------------------------------------------------------------------
// Device-global scratch (no allocations allowed)
// ---------------------------------------------------------------------------
__device__ float  g_scores[(size_t)BB * LQ * LK];                 // 268 MB (unscaled)
__device__ float  g_rowinv[(size_t)BB * LQ];                      // per-row 1/Z
__device__ __half g_Qh[(size_t)BB * LQ * DD];
__device__ __half g_Ql[(size_t)BB * LQ * DD];
__device__ __half g_Kh[(size_t)BB * LK * DD];
__device__ __half g_Kl[(size_t)BB * LK * DD];
__device__ __half g_Vth[(size_t)BB * DD * LK];                    // V^T [b,d,k]
__device__ __half g_Vtl[(size_t)BB * DD * LK];
__device__ __half g_Ph[(size_t)BB * LQ * LK];                     // unnormalized exp
__device__ __half g_Pl[(size_t)BB * LQ * LK];

// ---------------------------------------------------------------------------
// PTX helpers
// ---------------------------------------------------------------------------
__device__ __forceinline__ uint32_t smem_u32(const void* p) {
    uint32_t a;
    asm("{ .reg .u64 t; cvta.to.shared.u64 t, %1; cvt.u32.u64 %0, t; }" : "=r"(a) : "l"(p));
    return a;
}
__device__ __forceinline__ void cp16(uint32_t s, const void* g) {
    asm volatile("cp.async.cg.shared.global [%0], [%1], 16;" :: "r"(s), "l"(g));
}
__device__ __forceinline__ void cp_commit() { asm volatile("cp.async.commit_group;" ::: "memory"); }
__device__ __forceinline__ void cp_wait0()  { asm volatile("cp.async.wait_group 0;" ::: "memory"); }
__device__ __forceinline__ void cp_wait1()  { asm volatile("cp.async.wait_group 1;" ::: "memory"); }

__device__ __forceinline__ void ldsm4(uint32_t* r, uint32_t addr) {
    asm volatile("ldmatrix.sync.aligned.m8n8.x4.shared.b16 {%0,%1,%2,%3}, [%4];"
                 : "=r"(r[0]), "=r"(r[1]), "=r"(r[2]), "=r"(r[3]) : "r"(addr));
}
__device__ __forceinline__ void mma_f16(float* c, const uint32_t* a, const uint32_t* b) {
    asm volatile("mma.sync.aligned.m16n8k16.row.col.f32.f16.f16.f32 "
                 "{%0,%1,%2,%3}, {%4,%5,%6,%7}, {%8,%9}, {%0,%1,%2,%3};"
                 : "+f"(c[0]), "+f"(c[1]), "+f"(c[2]), "+f"(c[3])
                 : "r"(a[0]), "r"(a[1]), "r"(a[2]), "r"(a[3]), "r"(b[0]), "r"(b[1]));
}

// ---------------------------------------------------------------------------
// HMMA GEMM (fp16 hi/lo, 3 terms): C = (Ah+Al)(Bh+Bl)^T ~= AhBh + AhBl + AlBh
// Block tile 128x128, BK=32, 8 warps (warp tile 64x32), 2 CTAs/SM.
// Optional per-row output scale (rowScale != nullptr -> C[m,:] *= rowScale[b*LQ+m]).
// ---------------------------------------------------------------------------
#define MAT_BYTES 8192
#define BUF_BYTES (4 * MAT_BYTES)       // 32 KB
#define GEMM_SMEM (2 * BUF_BYTES)       // 64 KB

__device__ __forceinline__ void load_buf(uint32_t sbase,
    const __half* __restrict__ Ah, const __half* __restrict__ Al, long ldA,
    const __half* __restrict__ Bh, const __half* __restrict__ Bl, long ldB,
    int kk, int tid)
{
    const int r0 = tid >> 2;            // 0..63
    const int c  = tid & 3;
#pragma unroll
    for (int p = 0; p < 2; p++) {
        const int r = r0 + p * 64;
        const uint32_t soff = r * 64 + ((c ^ ((r >> 1) & 3)) << 4);
        const size_t goffA = (size_t)r * ldA + kk + c * 8;
        const size_t goffB = (size_t)r * ldB + kk + c * 8;
        cp16(sbase + soff,                 Ah + goffA);
        cp16(sbase + MAT_BYTES + soff,     Al + goffA);
        cp16(sbase + 2 * MAT_BYTES + soff, Bh + goffB);
        cp16(sbase + 3 * MAT_BYTES + soff, Bl + goffB);
    }
}

__global__ __launch_bounds__(256, 2)
void hmma_gemm(const __half* __restrict__ Ah, const __half* __restrict__ Al,
               long ldA, long strideA,
               const __half* __restrict__ Bh, const __half* __restrict__ Bl,
               long ldB, long strideB,
               float* __restrict__ C, long ldC, long strideC, int Ktot,
               const float* __restrict__ rowScale)
{
    extern __shared__ char smem[];
    const uint32_t sbase = smem_u32(smem);

    const int tid  = threadIdx.x;
    const int lane = tid & 31, warp = tid >> 5;
    const int wm = (warp >> 2) * 64;      // 2 m-groups of 64 rows
    const int wn = (warp & 3) * 32;       // 4 n-groups of 32 cols
    const int b  = blockIdx.z;
    const int n0 = blockIdx.x * 128, m0 = blockIdx.y * 128;

    const __half* pAh = Ah + (size_t)b * strideA + (size_t)m0 * ldA;
    const __half* pAl = Al + (size_t)b * strideA + (size_t)m0 * ldA;
    const __half* pBh = Bh + (size_t)b * strideB + (size_t)n0 * ldB;
    const __half* pBl = Bl + (size_t)b * strideB + (size_t)n0 * ldB;

    const int aRow = (lane & 7) | (((lane >> 3) & 1) << 3);
    const int aCk  = (lane >> 4) & 1;
    const int bRow = (lane & 7) | (((lane >> 4) & 1) << 3);
    const int bCk  = (lane >> 3) & 1;

    float acc[4][4][4];
#pragma unroll
    for (int i = 0; i < 4; i++)
#pragma unroll
        for (int j = 0; j < 4; j++)
#pragma unroll
            for (int t = 0; t < 4; t++) acc[i][j][t] = 0.f;

    const int nc = Ktot / 32;

    load_buf(sbase, pAh, pAl, ldA, pBh, pBl, ldB, 0, tid);
    cp_commit();

    for (int c = 0; c < nc; c++) {
        if (c + 1 < nc) {
            load_buf(sbase + ((c + 1) & 1) * BUF_BYTES, pAh, pAl, ldA, pBh, pBl, ldB,
                     (c + 1) * 32, tid);
            cp_commit();
            cp_wait1();
        } else {
            cp_wait0();
        }
        __syncthreads();

        const uint32_t bb = sbase + (c & 1) * BUF_BYTES;
#pragma unroll
        for (int s = 0; s < 2; s++) {
            uint32_t bh[2][4], bl[2][4];
#pragma unroll
            for (int np = 0; np < 2; np++) {
                const int r = wn + np * 16 + bRow;
                const int ck = s * 2 + bCk;
                const uint32_t off = r * 64 + ((ck ^ ((r >> 1) & 3)) << 4);
                ldsm4(bh[np], bb + 2 * MAT_BYTES + off);
                ldsm4(bl[np], bb + 3 * MAT_BYTES + off);
            }
#pragma unroll
            for (int mh = 0; mh < 2; mh++) {
                uint32_t ah[2][4], al[2][4];
#pragma unroll
                for (int mi = 0; mi < 2; mi++) {
                    const int r = wm + mh * 32 + mi * 16 + aRow;
                    const int ck = s * 2 + aCk;
                    const uint32_t off = r * 64 + ((ck ^ ((r >> 1) & 3)) << 4);
                    ldsm4(ah[mi], bb + off);
                    ldsm4(al[mi], bb + MAT_BYTES + off);
                }
#pragma unroll
                for (int mi = 0; mi < 2; mi++)
#pragma unroll
                    for (int nj = 0; nj < 4; nj++)
                        mma_f16(acc[mh * 2 + mi][nj], ah[mi], &bh[nj >> 1][(nj & 1) * 2]);
#pragma unroll
                for (int mi = 0; mi < 2; mi++)
#pragma unroll
                    for (int nj = 0; nj < 4; nj++)
                        mma_f16(acc[mh * 2 + mi][nj], ah[mi], &bl[nj >> 1][(nj & 1) * 2]);
#pragma unroll
                for (int mi = 0; mi < 2; mi++)
#pragma unroll
                    for (int nj = 0; nj < 4; nj++)
                        mma_f16(acc[mh * 2 + mi][nj], al[mi], &bh[nj >> 1][(nj & 1) * 2]);
            }
        }
        __syncthreads();
    }

    const int g = lane >> 2, tg = lane & 3;
    float* Cb = C + (size_t)b * strideC;
    const float* rs = rowScale ? rowScale + (size_t)b * LQ : nullptr;
#pragma unroll
    for (int mi = 0; mi < 4; mi++) {
        const int row = m0 + wm + mi * 16 + g;
        const float sA = rs ? rs[row]     : 1.f;
        const float sB = rs ? rs[row + 8] : 1.f;
#pragma unroll
        for (int nj = 0; nj < 4; nj++) {
            const int col = n0 + wn + nj * 8 + tg * 2;
            *(float2*)(Cb + (size_t)row * ldC + col) =
                make_float2(acc[mi][nj][0] * sA, acc[mi][nj][1] * sA);
            *(float2*)(Cb + (size_t)(row + 8) * ldC + col) =
                make_float2(acc[mi][nj][2] * sB, acc[mi][nj][3] * sB);
        }
    }
}

// ---------------------------------------------------------------------------
// fp32 -> (hi, lo) fp16 split (no scale: applied in softmax)
// ---------------------------------------------------------------------------
__global__ void split_kernel(const float4* __restrict__ in,
                             __half* __restrict__ hi,
                             __half* __restrict__ lo, int n4)
{
    int i = blockIdx.x * blockDim.x + threadIdx.x;
    if (i >= n4) return;
    float4 v = in[i];
    __half h0 = __float2half_rn(v.x), h1 = __float2half_rn(v.y);
    __half h2 = __float2half_rn(v.z), h3 = __float2half_rn(v.w);
    __half l0 = __float2half_rn(v.x - __half2float(h0));
    __half l1 = __float2half_rn(v.y - __half2float(h1));
    __half l2 = __float2half_rn(v.z - __half2float(h2));
    __half l3 = __float2half_rn(v.w - __half2float(h3));
    uint2 hv, lv;
    hv.x = (uint32_t)__half_as_ushort(h0) | ((uint32_t)__half_as_ushort(h1) << 16);
    hv.y = (uint32_t)__half_as_ushort(h2) | ((uint32_t)__half_as_ushort(h3) << 16);
    lv.x = (uint32_t)__half_as_ushort(l0) | ((uint32_t)__half_as_ushort(l1) << 16);
    lv.y = (uint32_t)__half_as_ushort(l2) | ((uint32_t)__half_as_ushort(l3) << 16);
    *(uint2*)(hi + 4 * (size_t)i) = hv;
    *(uint2*)(lo + 4 * (size_t)i) = lv;
}

// ---------------------------------------------------------------------------
// Transpose V [b,k,d] -> Vt [b,d,k], split hi/lo fp16
// ---------------------------------------------------------------------------
__global__ void vt_split(const float* __restrict__ V)
{
    __shared__ float tile[32][33];
    const int b = blockIdx.z;
    const int k0 = blockIdx.x * 32, d0 = blockIdx.y * 32;
    const float* Vb = V + (size_t)b * LK * DD;
#pragma unroll
    for (int i = threadIdx.y; i < 32; i += 8)
        tile[i][threadIdx.x] = Vb[(size_t)(k0 + i) * DD + d0 + threadIdx.x];
    __syncthreads();
#pragma unroll
    for (int i = threadIdx.y; i < 32; i += 8) {
        float x = tile[threadIdx.x][i];
        size_t o = (size_t)b * DD * LK + (size_t)(d0 + i) * LK + k0 + threadIdx.x;
        __half h = __float2half_rn(x);
        g_Vth[o] = h;
        g_Vtl[o] = __float2half_rn(x - __half2float(h));
    }
}

// ---------------------------------------------------------------------------
// Top-k (exact 512th-largest via MSB radix select with candidate compaction)
// + sparse softmax on UNSCALED scores (selection is scale-monotone).
// Writes UNNORMALIZED exp to Ph/Pl and 1/Z to g_rowinv.
// ---------------------------------------------------------------------------
__device__ __forceinline__ unsigned fkey(float x) {
    unsigned u = __float_as_uint(x);
    return u ^ ((u >> 31) ? 0xFFFFFFFFu : 0x80000000u);
}
__device__ __forceinline__ float fkey_inv(unsigned u) {
    unsigned bits = (u >> 31) ? (u ^ 0x80000000u) : ~u;
    return __uint_as_float(bits);
}

#define CAND_CAP 1024
#define SM_SCALE 0.04419417382415922f   // 1/sqrt(512)

__global__ __launch_bounds__(256)
void topk_softmax(void)
{
    __shared__ float row[LK];            // 8 KB
    __shared__ float cand[CAND_CAP];     // 4 KB
    __shared__ unsigned hist[256];
    __shared__ float redf[8];
    __shared__ float s_bcast;
    __shared__ int s_bin, s_k, s_cnt;

    const int tid = threadIdx.x;
    const int lane = tid & 31, wid = tid >> 5;
    const float* Srow = g_scores + (size_t)blockIdx.x * LK;
    __half* PhR = g_Ph + (size_t)blockIdx.x * LK;
    __half* PlR = g_Pl + (size_t)blockIdx.x * LK;

    if (tid < 256) hist[tid] = 0;
    if (tid == 0) s_cnt = 0;
    __syncthreads();

    // ---- load + rowmax + pass-0 histogram (bits 31:24), one scan ----
    float m = -3.4e38f;
    for (int i = tid; i < LK / 4; i += 256) {
        float4 v = ((const float4*)Srow)[i];
        ((float4*)row)[i] = v;
        m = fmaxf(fmaxf(m, v.x), fmaxf(v.y, v.z));
        m = fmaxf(m, v.w);
        atomicAdd(&hist[fkey(v.x) >> 24], 1u);
        atomicAdd(&hist[fkey(v.y) >> 24], 1u);
        atomicAdd(&hist[fkey(v.z) >> 24], 1u);
        atomicAdd(&hist[fkey(v.w) >> 24], 1u);
    }
#pragma unroll
    for (int o = 16; o > 0; o >>= 1) m = fmaxf(m, __shfl_xor_sync(0xFFFFFFFFu, m, o));
    if (lane == 0) redf[wid] = m;
    __syncthreads();
    if (tid == 0) {
        float mm = redf[0];
#pragma unroll
        for (int i = 1; i < 8; i++) mm = fmaxf(mm, redf[i]);
        s_bcast = mm;
    }

    unsigned prefix = 0;
    int k = TOPK;

#define SELECT_BIN()                                                            \
    do {                                                                        \
        if (wid == 0) {                                                         \
            unsigned h[8], tot = 0;                                             \
            for (int j = 0; j < 8; j++) { h[j] = hist[lane * 8 + j]; tot += h[j]; } \
            unsigned suf = tot;                                                 \
            for (int o = 1; o < 32; o <<= 1) {                                  \
                unsigned v = __shfl_down_sync(0xFFFFFFFFu, suf, o);             \
                if (lane + o < 32) suf += v;                                    \
            }                                                                   \
            unsigned run = suf - tot;                                           \
            for (int j = 7; j >= 0; j--) {                                      \
                unsigned cge = run + h[j];                                      \
                if (cge >= (unsigned)k && run < (unsigned)k) {                  \
                    s_bin = lane * 8 + j;                                       \
                    s_k = k - (int)run;                                         \
                }                                                               \
                run = cge;                                                      \
            }                                                                   \
        }                                                                       \
    } while (0)

    __syncthreads();
    SELECT_BIN();
    __syncthreads();
    prefix = (unsigned)s_bin << 24;
    k = s_k;
    const float rowmax = s_bcast;
    __syncthreads();

    // ---- pass 1 (bits 23:16): scan full row, compact candidates ----
    if (tid < 256) hist[tid] = 0;
    __syncthreads();
    for (int i = tid; i < LK; i += 256) {
        float x = row[i];
        unsigned u = fkey(x);
        if ((u >> 24) == (prefix >> 24)) {
            int idx = atomicAdd(&s_cnt, 1);
            if (idx < CAND_CAP) cand[idx] = x;
            atomicAdd(&hist[(u >> 16) & 0xFF], 1u);
        }
    }
    __syncthreads();
    SELECT_BIN();
    __syncthreads();
    prefix |= (unsigned)s_bin << 16;
    k = s_k;
    const int ncand = s_cnt;
    const bool uselist = (ncand <= CAND_CAP);
    __syncthreads();

    // ---- passes 2,3 over candidate list (or full row on overflow) ----
#pragma unroll
    for (int pass = 2; pass < 4; pass++) {
        const int shift = 24 - pass * 8;
        const unsigned mask = 0xFFFFFFFFu << (32 - 8 * pass);
        if (tid < 256) hist[tid] = 0;
        __syncthreads();
        if (uselist) {
            for (int i = tid; i < ncand; i += 256) {
                unsigned u = fkey(cand[i]);
                if ((u & mask) == prefix)
                    atomicAdd(&hist[(u >> shift) & 0xFF], 1u);
            }
        } else {
            for (int i = tid; i < LK; i += 256) {
                unsigned u = fkey(row[i]);
                if ((u & mask) == prefix)
                    atomicAdd(&hist[(u >> shift) & 0xFF], 1u);
            }
        }
        __syncthreads();
        SELECT_BIN();
        __syncthreads();
        prefix |= (unsigned)s_bin << shift;
        k = s_k;
        __syncthreads();
    }
    const float tau = fkey_inv(prefix);

    // ---- fused: write unnormalized exp (fp16 hi/lo) + accumulate sum ----
    float ssum = 0.f;
    for (int i = tid; i < LK; i += 256) {
        float x = row[i];
        float p = (x >= tau) ? __expf((x - rowmax) * SM_SCALE) : 0.f;
        ssum += p;
        __half h = __float2half_rn(p);
        PhR[i] = h;
        PlR[i] = __float2half_rn(p - __half2float(h));
    }
#pragma unroll
    for (int o = 16; o > 0; o >>= 1) ssum += __shfl_xor_sync(0xFFFFFFFFu, ssum, o);
    if (lane == 0) redf[wid] = ssum;
    __syncthreads();
    if (tid == 0) {
        float t = 0.f;
#pragma unroll
        for (int i = 0; i < 8; i++) t += redf[i];
        g_rowinv[blockIdx.x] = 1.0f / t;
    }
#undef SELECT_BIN
}

// ---------------------------------------------------------------------------
extern "C" void kernel_launch(void* const* d_in, const int* in_sizes, int n_in,
                              void* d_out, int out_size)
{
    const float* Q = (const float*)d_in[0];
    const float* K = (const float*)d_in[1];
    const float* V = (const float*)d_in[2];
    float* O = (float*)d_out;

    cudaFuncSetAttribute(hmma_gemm, cudaFuncAttributeMaxDynamicSharedMemorySize, GEMM_SMEM);

    void *pQh, *pQl, *pKh, *pKl, *pVth, *pVtl, *pPh, *pPl, *pS, *pRI;
    cudaGetSymbolAddress(&pQh, g_Qh);   cudaGetSymbolAddress(&pQl, g_Ql);
    cudaGetSymbolAddress(&pKh, g_Kh);   cudaGetSymbolAddress(&pKl, g_Kl);
    cudaGetSymbolAddress(&pVth, g_Vth); cudaGetSymbolAddress(&pVtl, g_Vtl);
    cudaGetSymbolAddress(&pPh, g_Ph);   cudaGetSymbolAddress(&pPl, g_Pl);
    cudaGetSymbolAddress(&pS, g_scores);
    cudaGetSymbolAddress(&pRI, g_rowinv);

    const int n4 = (BB * LQ * DD) / 4;

    split_kernel<<<(n4 + 255) / 256, 256>>>((const float4*)Q,
        (__half*)pQh, (__half*)pQl, n4);
    split_kernel<<<(n4 + 255) / 256, 256>>>((const float4*)K,
        (__half*)pKh, (__half*)pKl, n4);

    dim3 tb(32, 8), tg(LK / 32, DD / 32, BB);
    vt_split<<<tg, tb>>>(V);

    // scores = Q @ K^T (UNSCALED; scale applied in softmax — selection is monotone)
    hmma_gemm<<<dim3(LK / 128, LQ / 128, BB), 256, GEMM_SMEM>>>(
        (const __half*)pQh, (const __half*)pQl, DD, (long)LQ * DD,
        (const __half*)pKh, (const __half*)pKl, DD, (long)LK * DD,
        (float*)pS, LK, (long)LQ * LK, DD, nullptr);

    topk_softmax<<<BB * LQ, 256>>>();

    // O = diag(1/Z) * (P_unnorm @ V)   (V pre-transposed to [b,d,k])
    hmma_gemm<<<dim3(DD / 128, LQ / 128, BB), 256, GEMM_SMEM>>>(
        (const __half*)pPh, (const __half*)pPl, LK, (long)LQ * LK,
        (const __half*)pVth, (const __half*)pVtl, LK, (long)DD * LK,
        O, DD, (long)LQ * DD, LK, (const float*)pRI);
}

// round 10
// speedup vs baseline: 1.2689x; 1.0146x over previous
#include <cuda_runtime.h>
#include <cuda_fp16.h>
#include <cstdint>

#define BB 16
#define LQ 2048
#define LK 2048
#define DD 512
#define TOPK 512

// ---------------------------------------------------------------------------
// Device-global scratch (no allocations allowed)
// ---------------------------------------------------------------------------
__device__ float  g_scores[(size_t)BB * LQ * LK];                 // 268 MB (unscaled)
__device__ float  g_rowinv[(size_t)BB * LQ];                      // per-row 1/Z
__device__ __half g_Qh[(size_t)BB * LQ * DD];
__device__ __half g_Ql[(size_t)BB * LQ * DD];
__device__ __half g_Kh[(size_t)BB * LK * DD];
__device__ __half g_Kl[(size_t)BB * LK * DD];
__device__ __half g_Vth[(size_t)BB * DD * LK];                    // V^T [b,d,k]
__device__ __half g_Vtl[(size_t)BB * DD * LK];
__device__ __half g_Ph[(size_t)BB * LQ * LK];                     // unnormalized exp
__device__ __half g_Pl[(size_t)BB * LQ * LK];

// ---------------------------------------------------------------------------
// PTX helpers
// ---------------------------------------------------------------------------
__device__ __forceinline__ uint32_t smem_u32(const void* p) {
    uint32_t a;
    asm("{ .reg .u64 t; cvta.to.shared.u64 t, %1; cvt.u32.u64 %0, t; }" : "=r"(a) : "l"(p));
    return a;
}
__device__ __forceinline__ void cp16(uint32_t s, const void* g) {
    asm volatile("cp.async.cg.shared.global [%0], [%1], 16;" :: "r"(s), "l"(g));
}
__device__ __forceinline__ void cp_commit() { asm volatile("cp.async.commit_group;" ::: "memory"); }
__device__ __forceinline__ void cp_wait0()  { asm volatile("cp.async.wait_group 0;" ::: "memory"); }
__device__ __forceinline__ void cp_wait1()  { asm volatile("cp.async.wait_group 1;" ::: "memory"); }
__device__ __forceinline__ void cp_wait2()  { asm volatile("cp.async.wait_group 2;" ::: "memory"); }

__device__ __forceinline__ void ldsm4(uint32_t* r, uint32_t addr) {
    asm volatile("ldmatrix.sync.aligned.m8n8.x4.shared.b16 {%0,%1,%2,%3}, [%4];"
                 : "=r"(r[0]), "=r"(r[1]), "=r"(r[2]), "=r"(r[3]) : "r"(addr));
}
__device__ __forceinline__ void mma_f16(float* c, const uint32_t* a, const uint32_t* b) {
    asm volatile("mma.sync.aligned.m16n8k16.row.col.f32.f16.f16.f32 "
                 "{%0,%1,%2,%3}, {%4,%5,%6,%7}, {%8,%9}, {%0,%1,%2,%3};"
                 : "+f"(c[0]), "+f"(c[1]), "+f"(c[2]), "+f"(c[3])
                 : "r"(a[0]), "r"(a[1]), "r"(a[2]), "r"(a[3]), "r"(b[0]), "r"(b[1]));
}

// ---------------------------------------------------------------------------
// HMMA GEMM (fp16 hi/lo, 3 terms): C = (Ah+Al)(Bh+Bl)^T ~= AhBh + AhBl + AlBh
// Block tile 128x128, BK=32, 8 warps (warp tile 64x32), 2 CTAs/SM.
// TRIPLE-buffered cp.async pipeline (wait targets chunk committed 2 iters back).
// Optional per-row output scale (rowScale != nullptr -> C[m,:] *= rowScale[b*LQ+m]).
// ---------------------------------------------------------------------------
#define MAT_BYTES 8192
#define BUF_BYTES (4 * MAT_BYTES)       // 32 KB
#define NSTAGE 3
#define GEMM_SMEM (NSTAGE * BUF_BYTES)  // 96 KB

__device__ __forceinline__ void load_buf(uint32_t sbase,
    const __half* __restrict__ Ah, const __half* __restrict__ Al, long ldA,
    const __half* __restrict__ Bh, const __half* __restrict__ Bl, long ldB,
    int kk, int tid)
{
    const int r0 = tid >> 2;            // 0..63
    const int c  = tid & 3;
#pragma unroll
    for (int p = 0; p < 2; p++) {
        const int r = r0 + p * 64;
        const uint32_t soff = r * 64 + ((c ^ ((r >> 1) & 3)) << 4);
        const size_t goffA = (size_t)r * ldA + kk + c * 8;
        const size_t goffB = (size_t)r * ldB + kk + c * 8;
        cp16(sbase + soff,                 Ah + goffA);
        cp16(sbase + MAT_BYTES + soff,     Al + goffA);
        cp16(sbase + 2 * MAT_BYTES + soff, Bh + goffB);
        cp16(sbase + 3 * MAT_BYTES + soff, Bl + goffB);
    }
}

__global__ __launch_bounds__(256, 2)
void hmma_gemm(const __half* __restrict__ Ah, const __half* __restrict__ Al,
               long ldA, long strideA,
               const __half* __restrict__ Bh, const __half* __restrict__ Bl,
               long ldB, long strideB,
               float* __restrict__ C, long ldC, long strideC, int Ktot,
               const float* __restrict__ rowScale)
{
    extern __shared__ char smem[];
    const uint32_t sbase = smem_u32(smem);

    const int tid  = threadIdx.x;
    const int lane = tid & 31, warp = tid >> 5;
    const int wm = (warp >> 2) * 64;      // 2 m-groups of 64 rows
    const int wn = (warp & 3) * 32;       // 4 n-groups of 32 cols
    const int b  = blockIdx.z;
    const int n0 = blockIdx.x * 128, m0 = blockIdx.y * 128;

    const __half* pAh = Ah + (size_t)b * strideA + (size_t)m0 * ldA;
    const __half* pAl = Al + (size_t)b * strideA + (size_t)m0 * ldA;
    const __half* pBh = Bh + (size_t)b * strideB + (size_t)n0 * ldB;
    const __half* pBl = Bl + (size_t)b * strideB + (size_t)n0 * ldB;

    const int aRow = (lane & 7) | (((lane >> 3) & 1) << 3);
    const int aCk  = (lane >> 4) & 1;
    const int bRow = (lane & 7) | (((lane >> 4) & 1) << 3);
    const int bCk  = (lane >> 3) & 1;

    float acc[4][4][4];
#pragma unroll
    for (int i = 0; i < 4; i++)
#pragma unroll
        for (int j = 0; j < 4; j++)
#pragma unroll
            for (int t = 0; t < 4; t++) acc[i][j][t] = 0.f;

    const int nc = Ktot / 32;

    load_buf(sbase, pAh, pAl, ldA, pBh, pBl, ldB, 0, tid);
    cp_commit();
    if (nc > 1) {
        load_buf(sbase + BUF_BYTES, pAh, pAl, ldA, pBh, pBl, ldB, 32, tid);
        cp_commit();
    }

    int stage = 0;
    for (int c = 0; c < nc; c++) {
        if (c + 2 < nc) {
            int ls = stage + 2; if (ls >= NSTAGE) ls -= NSTAGE;
            load_buf(sbase + ls * BUF_BYTES, pAh, pAl, ldA, pBh, pBl, ldB,
                     (c + 2) * 32, tid);
            cp_commit();
            cp_wait2();
        } else if (c + 1 < nc) {
            cp_wait1();
        } else {
            cp_wait0();
        }
        __syncthreads();

        const uint32_t bb = sbase + stage * BUF_BYTES;
#pragma unroll
        for (int s = 0; s < 2; s++) {
            uint32_t bh[2][4], bl[2][4];
#pragma unroll
            for (int np = 0; np < 2; np++) {
                const int r = wn + np * 16 + bRow;
                const int ck = s * 2 + bCk;
                const uint32_t off = r * 64 + ((ck ^ ((r >> 1) & 3)) << 4);
                ldsm4(bh[np], bb + 2 * MAT_BYTES + off);
                ldsm4(bl[np], bb + 3 * MAT_BYTES + off);
            }
#pragma unroll
            for (int mh = 0; mh < 2; mh++) {
                uint32_t ah[2][4], al[2][4];
#pragma unroll
                for (int mi = 0; mi < 2; mi++) {
                    const int r = wm + mh * 32 + mi * 16 + aRow;
                    const int ck = s * 2 + aCk;
                    const uint32_t off = r * 64 + ((ck ^ ((r >> 1) & 3)) << 4);
                    ldsm4(ah[mi], bb + off);
                    ldsm4(al[mi], bb + MAT_BYTES + off);
                }
#pragma unroll
                for (int mi = 0; mi < 2; mi++)
#pragma unroll
                    for (int nj = 0; nj < 4; nj++)
                        mma_f16(acc[mh * 2 + mi][nj], ah[mi], &bh[nj >> 1][(nj & 1) * 2]);
#pragma unroll
                for (int mi = 0; mi < 2; mi++)
#pragma unroll
                    for (int nj = 0; nj < 4; nj++)
                        mma_f16(acc[mh * 2 + mi][nj], ah[mi], &bl[nj >> 1][(nj & 1) * 2]);
#pragma unroll
                for (int mi = 0; mi < 2; mi++)
#pragma unroll
                    for (int nj = 0; nj < 4; nj++)
                        mma_f16(acc[mh * 2 + mi][nj], al[mi], &bh[nj >> 1][(nj & 1) * 2]);
            }
        }
        __syncthreads();
        if (++stage == NSTAGE) stage = 0;
    }

    const int g = lane >> 2, tg = lane & 3;
    float* Cb = C + (size_t)b * strideC;
    const float* rs = rowScale ? rowScale + (size_t)b * LQ : nullptr;
#pragma unroll
    for (int mi = 0; mi < 4; mi++) {
        const int row = m0 + wm + mi * 16 + g;
        const float sA = rs ? rs[row]     : 1.f;
        const float sB = rs ? rs[row + 8] : 1.f;
#pragma unroll
        for (int nj = 0; nj < 4; nj++) {
            const int col = n0 + wn + nj * 8 + tg * 2;
            *(float2*)(Cb + (size_t)row * ldC + col) =
                make_float2(acc[mi][nj][0] * sA, acc[mi][nj][1] * sA);
            *(float2*)(Cb + (size_t)(row + 8) * ldC + col) =
                make_float2(acc[mi][nj][2] * sB, acc[mi][nj][3] * sB);
        }
    }
}

// ---------------------------------------------------------------------------
// fp32 -> (hi, lo) fp16 split (no scale: applied in softmax)
// ---------------------------------------------------------------------------
__global__ void split_kernel(const float4* __restrict__ in,
                             __half* __restrict__ hi,
                             __half* __restrict__ lo, int n4)
{
    int i = blockIdx.x * blockDim.x + threadIdx.x;
    if (i >= n4) return;
    float4 v = in[i];
    __half h0 = __float2half_rn(v.x), h1 = __float2half_rn(v.y);
    __half h2 = __float2half_rn(v.z), h3 = __float2half_rn(v.w);
    __half l0 = __float2half_rn(v.x - __half2float(h0));
    __half l1 = __float2half_rn(v.y - __half2float(h1));
    __half l2 = __float2half_rn(v.z - __half2float(h2));
    __half l3 = __float2half_rn(v.w - __half2float(h3));
    uint2 hv, lv;
    hv.x = (uint32_t)__half_as_ushort(h0) | ((uint32_t)__half_as_ushort(h1) << 16);
    hv.y = (uint32_t)__half_as_ushort(h2) | ((uint32_t)__half_as_ushort(h3) << 16);
    lv.x = (uint32_t)__half_as_ushort(l0) | ((uint32_t)__half_as_ushort(l1) << 16);
    lv.y = (uint32_t)__half_as_ushort(l2) | ((uint32_t)__half_as_ushort(l3) << 16);
    *(uint2*)(hi + 4 * (size_t)i) = hv;
    *(uint2*)(lo + 4 * (size_t)i) = lv;
}

// ---------------------------------------------------------------------------
// Transpose V [b,k,d] -> Vt [b,d,k], split hi/lo fp16
// ---------------------------------------------------------------------------
__global__ void vt_split(const float* __restrict__ V)
{
    __shared__ float tile[32][33];
    const int b = blockIdx.z;
    const int k0 = blockIdx.x * 32, d0 = blockIdx.y * 32;
    const float* Vb = V + (size_t)b * LK * DD;
#pragma unroll
    for (int i = threadIdx.y; i < 32; i += 8)
        tile[i][threadIdx.x] = Vb[(size_t)(k0 + i) * DD + d0 + threadIdx.x];
    __syncthreads();
#pragma unroll
    for (int i = threadIdx.y; i < 32; i += 8) {
        float x = tile[threadIdx.x][i];
        size_t o = (size_t)b * DD * LK + (size_t)(d0 + i) * LK + k0 + threadIdx.x;
        __half h = __float2half_rn(x);
        g_Vth[o] = h;
        g_Vtl[o] = __float2half_rn(x - __half2float(h));
    }
}

// ---------------------------------------------------------------------------
// Top-k (exact 512th-largest via MSB radix select with candidate compaction)
// + sparse softmax on UNSCALED scores (selection is scale-monotone).
// Writes UNNORMALIZED exp to Ph/Pl (vectorized) and 1/Z to g_rowinv.
// ---------------------------------------------------------------------------
__device__ __forceinline__ unsigned fkey(float x) {
    unsigned u = __float_as_uint(x);
    return u ^ ((u >> 31) ? 0xFFFFFFFFu : 0x80000000u);
}
__device__ __forceinline__ float fkey_inv(unsigned u) {
    unsigned bits = (u >> 31) ? (u ^ 0x80000000u) : ~u;
    return __uint_as_float(bits);
}

#define CAND_CAP 1024
#define SM_SCALE 0.04419417382415922f   // 1/sqrt(512)

__global__ __launch_bounds__(256)
void topk_softmax(void)
{
    __shared__ float row[LK];            // 8 KB
    __shared__ float cand[CAND_CAP];     // 4 KB
    __shared__ unsigned hist[256];
    __shared__ float redf[8];
    __shared__ float s_bcast;
    __shared__ int s_bin, s_k, s_cnt;

    const int tid = threadIdx.x;
    const int lane = tid & 31, wid = tid >> 5;
    const float* Srow = g_scores + (size_t)blockIdx.x * LK;
    __half* PhR = g_Ph + (size_t)blockIdx.x * LK;
    __half* PlR = g_Pl + (size_t)blockIdx.x * LK;

    if (tid < 256) hist[tid] = 0;
    if (tid == 0) s_cnt = 0;
    __syncthreads();

    // ---- load + rowmax + pass-0 histogram (bits 31:24), one scan ----
    float m = -3.4e38f;
    for (int i = tid; i < LK / 4; i += 256) {
        float4 v = ((const float4*)Srow)[i];
        ((float4*)row)[i] = v;
        m = fmaxf(fmaxf(m, v.x), fmaxf(v.y, v.z));
        m = fmaxf(m, v.w);
        atomicAdd(&hist[fkey(v.x) >> 24], 1u);
        atomicAdd(&hist[fkey(v.y) >> 24], 1u);
        atomicAdd(&hist[fkey(v.z) >> 24], 1u);
        atomicAdd(&hist[fkey(v.w) >> 24], 1u);
    }
#pragma unroll
    for (int o = 16; o > 0; o >>= 1) m = fmaxf(m, __shfl_xor_sync(0xFFFFFFFFu, m, o));
    if (lane == 0) redf[wid] = m;
    __syncthreads();
    if (tid == 0) {
        float mm = redf[0];
#pragma unroll
        for (int i = 1; i < 8; i++) mm = fmaxf(mm, redf[i]);
        s_bcast = mm;
    }

    unsigned prefix = 0;
    int k = TOPK;

#define SELECT_BIN()                                                            \
    do {                                                                        \
        if (wid == 0) {                                                         \
            unsigned h[8], tot = 0;                                             \
            for (int j = 0; j < 8; j++) { h[j] = hist[lane * 8 + j]; tot += h[j]; } \
            unsigned suf = tot;                                                 \
            for (int o = 1; o < 32; o <<= 1) {                                  \
                unsigned v = __shfl_down_sync(0xFFFFFFFFu, suf, o);             \
                if (lane + o < 32) suf += v;                                    \
            }                                                                   \
            unsigned run = suf - tot;                                           \
            for (int j = 7; j >= 0; j--) {                                      \
                unsigned cge = run + h[j];                                      \
                if (cge >= (unsigned)k && run < (unsigned)k) {                  \
                    s_bin = lane * 8 + j;                                       \
                    s_k = k - (int)run;                                         \
                }                                                               \
                run = cge;                                                      \
            }                                                                   \
        }                                                                       \
    } while (0)

    __syncthreads();
    SELECT_BIN();
    __syncthreads();
    prefix = (unsigned)s_bin << 24;
    k = s_k;
    const float rowmax = s_bcast;
    __syncthreads();

    // ---- pass 1 (bits 23:16): scan full row, compact candidates ----
    if (tid < 256) hist[tid] = 0;
    __syncthreads();
    for (int i = tid; i < LK; i += 256) {
        float x = row[i];
        unsigned u = fkey(x);
        if ((u >> 24) == (prefix >> 24)) {
            int idx = atomicAdd(&s_cnt, 1);
            if (idx < CAND_CAP) cand[idx] = x;
            atomicAdd(&hist[(u >> 16) & 0xFF], 1u);
        }
    }
    __syncthreads();
    SELECT_BIN();
    __syncthreads();
    prefix |= (unsigned)s_bin << 16;
    k = s_k;
    const int ncand = s_cnt;
    const bool uselist = (ncand <= CAND_CAP);
    __syncthreads();

    // ---- passes 2,3 over candidate list (or full row on overflow) ----
#pragma unroll
    for (int pass = 2; pass < 4; pass++) {
        const int shift = 24 - pass * 8;
        const unsigned mask = 0xFFFFFFFFu << (32 - 8 * pass);
        if (tid < 256) hist[tid] = 0;
        __syncthreads();
        if (uselist) {
            for (int i = tid; i < ncand; i += 256) {
                unsigned u = fkey(cand[i]);
                if ((u & mask) == prefix)
                    atomicAdd(&hist[(u >> shift) & 0xFF], 1u);
            }
        } else {
            for (int i = tid; i < LK; i += 256) {
                unsigned u = fkey(row[i]);
                if ((u & mask) == prefix)
                    atomicAdd(&hist[(u >> shift) & 0xFF], 1u);
            }
        }
        __syncthreads();
        SELECT_BIN();
        __syncthreads();
        prefix |= (unsigned)s_bin << shift;
        k = s_k;
        __syncthreads();
    }
    const float tau = fkey_inv(prefix);

    // ---- fused: write unnormalized exp (fp16 hi/lo, VECTORIZED) + sum ----
    float ssum = 0.f;
    for (int i = tid; i < LK / 4; i += 256) {
        float4 v = ((const float4*)row)[i];
        float p0 = (v.x >= tau) ? __expf((v.x - rowmax) * SM_SCALE) : 0.f;
        float p1 = (v.y >= tau) ? __expf((v.y - rowmax) * SM_SCALE) : 0.f;
        float p2 = (v.z >= tau) ? __expf((v.z - rowmax) * SM_SCALE) : 0.f;
        float p3 = (v.w >= tau) ? __expf((v.w - rowmax) * SM_SCALE) : 0.f;
        ssum += (p0 + p1) + (p2 + p3);
        __half h0 = __float2half_rn(p0), h1 = __float2half_rn(p1);
        __half h2 = __float2half_rn(p2), h3 = __float2half_rn(p3);
        __half l0 = __float2half_rn(p0 - __half2float(h0));
        __half l1 = __float2half_rn(p1 - __half2float(h1));
        __half l2 = __float2half_rn(p2 - __half2float(h2));
        __half l3 = __float2half_rn(p3 - __half2float(h3));
        uint2 hv, lv;
        hv.x = (uint32_t)__half_as_ushort(h0) | ((uint32_t)__half_as_ushort(h1) << 16);
        hv.y = (uint32_t)__half_as_ushort(h2) | ((uint32_t)__half_as_ushort(h3) << 16);
        lv.x = (uint32_t)__half_as_ushort(l0) | ((uint32_t)__half_as_ushort(l1) << 16);
        lv.y = (uint32_t)__half_as_ushort(l2) | ((uint32_t)__half_as_ushort(l3) << 16);
        ((uint2*)PhR)[i] = hv;
        ((uint2*)PlR)[i] = lv;
    }
#pragma unroll
    for (int o = 16; o > 0; o >>= 1) ssum += __shfl_xor_sync(0xFFFFFFFFu, ssum, o);
    if (lane == 0) redf[wid] = ssum;
    __syncthreads();
    if (tid == 0) {
        float t = 0.f;
#pragma unroll
        for (int i = 0; i < 8; i++) t += redf[i];
        g_rowinv[blockIdx.x] = 1.0f / t;
    }
#undef SELECT_BIN
}

// ---------------------------------------------------------------------------
extern "C" void kernel_launch(void* const* d_in, const int* in_sizes, int n_in,
                              void* d_out, int out_size)
{
    const float* Q = (const float*)d_in[0];
    const float* K = (const float*)d_in[1];
    const float* V = (const float*)d_in[2];
    float* O = (float*)d_out;

    cudaFuncSetAttribute(hmma_gemm, cudaFuncAttributeMaxDynamicSharedMemorySize, GEMM_SMEM);

    void *pQh, *pQl, *pKh, *pKl, *pVth, *pVtl, *pPh, *pPl, *pS, *pRI;
    cudaGetSymbolAddress(&pQh, g_Qh);   cudaGetSymbolAddress(&pQl, g_Ql);
    cudaGetSymbolAddress(&pKh, g_Kh);   cudaGetSymbolAddress(&pKl, g_Kl);
    cudaGetSymbolAddress(&pVth, g_Vth); cudaGetSymbolAddress(&pVtl, g_Vtl);
    cudaGetSymbolAddress(&pPh, g_Ph);   cudaGetSymbolAddress(&pPl, g_Pl);
    cudaGetSymbolAddress(&pS, g_scores);
    cudaGetSymbolAddress(&pRI, g_rowinv);

    const int n4 = (BB * LQ * DD) / 4;

    split_kernel<<<(n4 + 255) / 256, 256>>>((const float4*)Q,
        (__half*)pQh, (__half*)pQl, n4);
    split_kernel<<<(n4 + 255) / 256, 256>>>((const float4*)K,
        (__half*)pKh, (__half*)pKl, n4);

    dim3 tb(32, 8), tg(LK / 32, DD / 32, BB);
    vt_split<<<tg, tb>>>(V);

    // scores = Q @ K^T (UNSCALED; scale applied in softmax — selection is monotone)
    hmma_gemm<<<dim3(LK / 128, LQ / 128, BB), 256, GEMM_SMEM>>>(
        (const __half*)pQh, (const __half*)pQl, DD, (long)LQ * DD,
        (const __half*)pKh, (const __half*)pKl, DD, (long)LK * DD,
        (float*)pS, LK, (long)LQ * LK, DD, nullptr);

    topk_softmax<<<BB * LQ, 256>>>();

    // O = diag(1/Z) * (P_unnorm @ V)   (V pre-transposed to [b,d,k])
    hmma_gemm<<<dim3(DD / 128, LQ / 128, BB), 256, GEMM_SMEM>>>(
        (const __half*)pPh, (const __half*)pPl, LK, (long)LQ * LK,
        (const __half*)pVth, (const __half*)pVtl, LK, (long)DD * LK,
        O, DD, (long)LQ * DD, LK, (const float*)pRI);
}

// round 11
// speedup vs baseline: 1.3175x; 1.0383x over previous
#include <cuda_runtime.h>
#include <cuda_fp16.h>
#include <cstdint>

#define BB 16
#define LQ 2048
#define LK 2048
#define DD 512
#define TOPK 512

// ---------------------------------------------------------------------------
// Device-global scratch (no allocations allowed)
// ---------------------------------------------------------------------------
__device__ float  g_scores[(size_t)BB * LQ * LK];                 // 268 MB (unscaled)
__device__ float  g_rowinv[(size_t)BB * LQ];                      // per-row 1/Z
__device__ __half g_Qh[(size_t)BB * LQ * DD];
__device__ __half g_Ql[(size_t)BB * LQ * DD];
__device__ __half g_Kh[(size_t)BB * LK * DD];
__device__ __half g_Kl[(size_t)BB * LK * DD];
__device__ __half g_Vth[(size_t)BB * DD * LK];                    // V^T [b,d,k]
__device__ __half g_Vtl[(size_t)BB * DD * LK];
__device__ __half g_Ph[(size_t)BB * LQ * LK];                     // unnormalized exp
__device__ __half g_Pl[(size_t)BB * LQ * LK];

// ---------------------------------------------------------------------------
// PTX helpers
// ---------------------------------------------------------------------------
__device__ __forceinline__ uint32_t smem_u32(const void* p) {
    uint32_t a;
    asm("{ .reg .u64 t; cvta.to.shared.u64 t, %1; cvt.u32.u64 %0, t; }" : "=r"(a) : "l"(p));
    return a;
}
__device__ __forceinline__ void cp16(uint32_t s, const void* g) {
    asm volatile("cp.async.cg.shared.global [%0], [%1], 16;" :: "r"(s), "l"(g));
}
__device__ __forceinline__ void cp_commit() { asm volatile("cp.async.commit_group;" ::: "memory"); }
__device__ __forceinline__ void cp_wait0()  { asm volatile("cp.async.wait_group 0;" ::: "memory"); }
__device__ __forceinline__ void cp_wait1()  { asm volatile("cp.async.wait_group 1;" ::: "memory"); }
__device__ __forceinline__ void cp_wait2()  { asm volatile("cp.async.wait_group 2;" ::: "memory"); }

__device__ __forceinline__ void ldsm4(uint32_t* r, uint32_t addr) {
    asm volatile("ldmatrix.sync.aligned.m8n8.x4.shared.b16 {%0,%1,%2,%3}, [%4];"
                 : "=r"(r[0]), "=r"(r[1]), "=r"(r[2]), "=r"(r[3]) : "r"(addr));
}
__device__ __forceinline__ void mma_f16(float* c, const uint32_t* a, const uint32_t* b) {
    asm volatile("mma.sync.aligned.m16n8k16.row.col.f32.f16.f16.f32 "
                 "{%0,%1,%2,%3}, {%4,%5,%6,%7}, {%8,%9}, {%0,%1,%2,%3};"
                 : "+f"(c[0]), "+f"(c[1]), "+f"(c[2]), "+f"(c[3])
                 : "r"(a[0]), "r"(a[1]), "r"(a[2]), "r"(a[3]), "r"(b[0]), "r"(b[1]));
}

// ---------------------------------------------------------------------------
// HMMA GEMM (fp16 hi/lo, 3 terms): unchanged from R10 (at mma.sync ceiling)
// ---------------------------------------------------------------------------
#define MAT_BYTES 8192
#define BUF_BYTES (4 * MAT_BYTES)       // 32 KB
#define NSTAGE 3
#define GEMM_SMEM (NSTAGE * BUF_BYTES)  // 96 KB

__device__ __forceinline__ void load_buf(uint32_t sbase,
    const __half* __restrict__ Ah, const __half* __restrict__ Al, long ldA,
    const __half* __restrict__ Bh, const __half* __restrict__ Bl, long ldB,
    int kk, int tid)
{
    const int r0 = tid >> 2;            // 0..63
    const int c  = tid & 3;
#pragma unroll
    for (int p = 0; p < 2; p++) {
        const int r = r0 + p * 64;
        const uint32_t soff = r * 64 + ((c ^ ((r >> 1) & 3)) << 4);
        const size_t goffA = (size_t)r * ldA + kk + c * 8;
        const size_t goffB = (size_t)r * ldB + kk + c * 8;
        cp16(sbase + soff,                 Ah + goffA);
        cp16(sbase + MAT_BYTES + soff,     Al + goffA);
        cp16(sbase + 2 * MAT_BYTES + soff, Bh + goffB);
        cp16(sbase + 3 * MAT_BYTES + soff, Bl + goffB);
    }
}

__global__ __launch_bounds__(256, 2)
void hmma_gemm(const __half* __restrict__ Ah, const __half* __restrict__ Al,
               long ldA, long strideA,
               const __half* __restrict__ Bh, const __half* __restrict__ Bl,
               long ldB, long strideB,
               float* __restrict__ C, long ldC, long strideC, int Ktot,
               const float* __restrict__ rowScale)
{
    extern __shared__ char smem[];
    const uint32_t sbase = smem_u32(smem);

    const int tid  = threadIdx.x;
    const int lane = tid & 31, warp = tid >> 5;
    const int wm = (warp >> 2) * 64;
    const int wn = (warp & 3) * 32;
    const int b  = blockIdx.z;
    const int n0 = blockIdx.x * 128, m0 = blockIdx.y * 128;

    const __half* pAh = Ah + (size_t)b * strideA + (size_t)m0 * ldA;
    const __half* pAl = Al + (size_t)b * strideA + (size_t)m0 * ldA;
    const __half* pBh = Bh + (size_t)b * strideB + (size_t)n0 * ldB;
    const __half* pBl = Bl + (size_t)b * strideB + (size_t)n0 * ldB;

    const int aRow = (lane & 7) | (((lane >> 3) & 1) << 3);
    const int aCk  = (lane >> 4) & 1;
    const int bRow = (lane & 7) | (((lane >> 4) & 1) << 3);
    const int bCk  = (lane >> 3) & 1;

    float acc[4][4][4];
#pragma unroll
    for (int i = 0; i < 4; i++)
#pragma unroll
        for (int j = 0; j < 4; j++)
#pragma unroll
            for (int t = 0; t < 4; t++) acc[i][j][t] = 0.f;

    const int nc = Ktot / 32;

    load_buf(sbase, pAh, pAl, ldA, pBh, pBl, ldB, 0, tid);
    cp_commit();
    if (nc > 1) {
        load_buf(sbase + BUF_BYTES, pAh, pAl, ldA, pBh, pBl, ldB, 32, tid);
        cp_commit();
    }

    int stage = 0;
    for (int c = 0; c < nc; c++) {
        if (c + 2 < nc) {
            int ls = stage + 2; if (ls >= NSTAGE) ls -= NSTAGE;
            load_buf(sbase + ls * BUF_BYTES, pAh, pAl, ldA, pBh, pBl, ldB,
                     (c + 2) * 32, tid);
            cp_commit();
            cp_wait2();
        } else if (c + 1 < nc) {
            cp_wait1();
        } else {
            cp_wait0();
        }
        __syncthreads();

        const uint32_t bb = sbase + stage * BUF_BYTES;
#pragma unroll
        for (int s = 0; s < 2; s++) {
            uint32_t bh[2][4], bl[2][4];
#pragma unroll
            for (int np = 0; np < 2; np++) {
                const int r = wn + np * 16 + bRow;
                const int ck = s * 2 + bCk;
                const uint32_t off = r * 64 + ((ck ^ ((r >> 1) & 3)) << 4);
                ldsm4(bh[np], bb + 2 * MAT_BYTES + off);
                ldsm4(bl[np], bb + 3 * MAT_BYTES + off);
            }
#pragma unroll
            for (int mh = 0; mh < 2; mh++) {
                uint32_t ah[2][4], al[2][4];
#pragma unroll
                for (int mi = 0; mi < 2; mi++) {
                    const int r = wm + mh * 32 + mi * 16 + aRow;
                    const int ck = s * 2 + aCk;
                    const uint32_t off = r * 64 + ((ck ^ ((r >> 1) & 3)) << 4);
                    ldsm4(ah[mi], bb + off);
                    ldsm4(al[mi], bb + MAT_BYTES + off);
                }
#pragma unroll
                for (int mi = 0; mi < 2; mi++)
#pragma unroll
                    for (int nj = 0; nj < 4; nj++)
                        mma_f16(acc[mh * 2 + mi][nj], ah[mi], &bh[nj >> 1][(nj & 1) * 2]);
#pragma unroll
                for (int mi = 0; mi < 2; mi++)
#pragma unroll
                    for (int nj = 0; nj < 4; nj++)
                        mma_f16(acc[mh * 2 + mi][nj], ah[mi], &bl[nj >> 1][(nj & 1) * 2]);
#pragma unroll
                for (int mi = 0; mi < 2; mi++)
#pragma unroll
                    for (int nj = 0; nj < 4; nj++)
                        mma_f16(acc[mh * 2 + mi][nj], al[mi], &bh[nj >> 1][(nj & 1) * 2]);
            }
        }
        __syncthreads();
        if (++stage == NSTAGE) stage = 0;
    }

    const int g = lane >> 2, tg = lane & 3;
    float* Cb = C + (size_t)b * strideC;
    const float* rs = rowScale ? rowScale + (size_t)b * LQ : nullptr;
#pragma unroll
    for (int mi = 0; mi < 4; mi++) {
        const int row = m0 + wm + mi * 16 + g;
        const float sA = rs ? rs[row]     : 1.f;
        const float sB = rs ? rs[row + 8] : 1.f;
#pragma unroll
        for (int nj = 0; nj < 4; nj++) {
            const int col = n0 + wn + nj * 8 + tg * 2;
            *(float2*)(Cb + (size_t)row * ldC + col) =
                make_float2(acc[mi][nj][0] * sA, acc[mi][nj][1] * sA);
            *(float2*)(Cb + (size_t)(row + 8) * ldC + col) =
                make_float2(acc[mi][nj][2] * sB, acc[mi][nj][3] * sB);
        }
    }
}

// ---------------------------------------------------------------------------
// fp32 -> (hi, lo) fp16 split, 8 elems/thread, uint4 stores
// ---------------------------------------------------------------------------
__global__ void split_kernel(const float4* __restrict__ in,
                             __half* __restrict__ hi,
                             __half* __restrict__ lo, int n8)
{
    int i = blockIdx.x * blockDim.x + threadIdx.x;
    if (i >= n8) return;
    float4 v0 = in[2 * i], v1 = in[2 * i + 1];
    float x[8] = { v0.x, v0.y, v0.z, v0.w, v1.x, v1.y, v1.z, v1.w };
    uint32_t hw[4], lw[4];
#pragma unroll
    for (int j = 0; j < 4; j++) {
        __half ha = __float2half_rn(x[2 * j]);
        __half hb = __float2half_rn(x[2 * j + 1]);
        __half la = __float2half_rn(x[2 * j] - __half2float(ha));
        __half lb = __float2half_rn(x[2 * j + 1] - __half2float(hb));
        hw[j] = (uint32_t)__half_as_ushort(ha) | ((uint32_t)__half_as_ushort(hb) << 16);
        lw[j] = (uint32_t)__half_as_ushort(la) | ((uint32_t)__half_as_ushort(lb) << 16);
    }
    *(uint4*)(hi + 8 * (size_t)i) = make_uint4(hw[0], hw[1], hw[2], hw[3]);
    *(uint4*)(lo + 8 * (size_t)i) = make_uint4(lw[0], lw[1], lw[2], lw[3]);
}

// ---------------------------------------------------------------------------
// Transpose V [b,k,d] -> Vt [b,d,k], split hi/lo fp16. 64k x 32d tiles,
// packed uint4 (8-half) stores.
// ---------------------------------------------------------------------------
__global__ __launch_bounds__(256)
void vt_split(const float* __restrict__ V)
{
    __shared__ float tile[64][33];
    const int b = blockIdx.z;
    const int k0 = blockIdx.x * 64, d0 = blockIdx.y * 32;
    const int tid = threadIdx.x;
    const float* Vb = V + (size_t)b * LK * DD;

    const int lx = tid & 31, lr = tid >> 5;
#pragma unroll
    for (int r = lr; r < 64; r += 8)
        tile[r][lx] = Vb[(size_t)(k0 + r) * DD + d0 + lx];
    __syncthreads();

    const int rr = tid >> 3;            // d-row 0..31
    const int kc = (tid & 7) * 8;       // k-chunk
    uint32_t hw[4], lw[4];
#pragma unroll
    for (int j = 0; j < 4; j++) {
        float xa = tile[kc + 2 * j][rr];
        float xb = tile[kc + 2 * j + 1][rr];
        __half ha = __float2half_rn(xa), hb = __float2half_rn(xb);
        __half la = __float2half_rn(xa - __half2float(ha));
        __half lb = __float2half_rn(xb - __half2float(hb));
        hw[j] = (uint32_t)__half_as_ushort(ha) | ((uint32_t)__half_as_ushort(hb) << 16);
        lw[j] = (uint32_t)__half_as_ushort(la) | ((uint32_t)__half_as_ushort(lb) << 16);
    }
    size_t o = (size_t)b * DD * LK + (size_t)(d0 + rr) * LK + k0 + kc;
    *(uint4*)(g_Vth + o) = make_uint4(hw[0], hw[1], hw[2], hw[3]);
    *(uint4*)(g_Vtl + o) = make_uint4(lw[0], lw[1], lw[2], lw[3]);
}

// ---------------------------------------------------------------------------
// Top-k + sparse softmax.
// New select: linear value-bucket prepass (low atomic contention, exact)
// -> tiny candidate list -> exact byte-radix on the list. Fallback to
// full-row radix on degenerate distributions. Same tau as before (exact).
// ---------------------------------------------------------------------------
__device__ __forceinline__ unsigned fkey(float x) {
    unsigned u = __float_as_uint(x);
    return u ^ ((u >> 31) ? 0xFFFFFFFFu : 0x80000000u);
}
__device__ __forceinline__ float fkey_inv(unsigned u) {
    unsigned bits = (u >> 31) ? (u ^ 0x80000000u) : ~u;
    return __uint_as_float(bits);
}

#define CAND_CAP 1024
#define SM_SCALE 0.04419417382415922f   // 1/sqrt(512)
#define BIN_INVW 2.0f                   // linear bin width 0.5, window 128

// warp-0 suffix-scan bin select over hist[256]; writes *ps_bin/*ps_k.
__device__ __forceinline__ void select_bin(const unsigned* hist, int k,
                                           int* ps_bin, int* ps_k,
                                           int lane, int wid)
{
    if (wid == 0) {
        unsigned h[8], tot = 0;
#pragma unroll
        for (int j = 0; j < 8; j++) { h[j] = hist[lane * 8 + j]; tot += h[j]; }
        unsigned suf = tot;
#pragma unroll
        for (int o = 1; o < 32; o <<= 1) {
            unsigned v = __shfl_down_sync(0xFFFFFFFFu, suf, o);
            if (lane + o < 32) suf += v;
        }
        unsigned run = suf - tot;
        for (int j = 7; j >= 0; j--) {
            unsigned cge = run + h[j];
            if (cge >= (unsigned)k && run < (unsigned)k) {
                *ps_bin = lane * 8 + j;
                *ps_k = k - (int)run;
            }
            run = cge;
        }
    }
}

// exact k-th-largest over arr[0..n) via 4-pass MSB byte radix (block-wide).
__device__ __forceinline__ float radix_select_dev(const float* arr, int n, int k,
                                                  unsigned* hist, int* ps_bin, int* ps_k,
                                                  int tid, int lane, int wid)
{
    unsigned prefix = 0;
#pragma unroll
    for (int pass = 0; pass < 4; pass++) {
        const int shift = 24 - pass * 8;
        const unsigned mask = pass ? (0xFFFFFFFFu << (32 - 8 * pass)) : 0u;
        if (tid < 256) hist[tid] = 0;
        __syncthreads();
        for (int i = tid; i < n; i += 256) {
            unsigned u = fkey(arr[i]);
            if ((u & mask) == prefix)
                atomicAdd(&hist[(u >> shift) & 0xFF], 1u);
        }
        __syncthreads();
        select_bin(hist, k, ps_bin, ps_k, lane, wid);
        __syncthreads();
        prefix |= ((unsigned)*ps_bin) << shift;
        k = *ps_k;
        __syncthreads();
    }
    return fkey_inv(prefix);
}

__global__ __launch_bounds__(256)
void topk_softmax(void)
{
    __shared__ float row[LK];            // 8 KB
    __shared__ float cand[CAND_CAP];     // 4 KB
    __shared__ unsigned hist[256];
    __shared__ float redf[8];
    __shared__ float s_bcast;
    __shared__ int s_bin, s_k, s_cnt;

    const int tid = threadIdx.x;
    const int lane = tid & 31, wid = tid >> 5;
    const float* Srow = g_scores + (size_t)blockIdx.x * LK;
    __half* PhR = g_Ph + (size_t)blockIdx.x * LK;
    __half* PlR = g_Pl + (size_t)blockIdx.x * LK;

    if (tid == 0) s_cnt = 0;

    // ---- scan 1: load + rowmax ----
    float m = -3.4e38f;
    for (int i = tid; i < LK / 4; i += 256) {
        float4 v = ((const float4*)Srow)[i];
        ((float4*)row)[i] = v;
        m = fmaxf(fmaxf(m, v.x), fmaxf(v.y, v.z));
        m = fmaxf(m, v.w);
    }
#pragma unroll
    for (int o = 16; o > 0; o >>= 1) m = fmaxf(m, __shfl_xor_sync(0xFFFFFFFFu, m, o));
    if (lane == 0) redf[wid] = m;
    __syncthreads();
    if (tid == 0) {
        float mm = redf[0];
#pragma unroll
        for (int i = 1; i < 8; i++) mm = fmaxf(mm, redf[i]);
        s_bcast = mm;
    }
    if (tid < 256) hist[tid] = 0;
    __syncthreads();
    const float rowmax = s_bcast;

    // ---- scan 2: linear-bucket histogram (bin 0 = top values) ----
    // stored flipped (hist[255 - bin]) so select_bin's high-bins-first works.
    for (int i = tid; i < LK; i += 256) {
        int bin = (int)((rowmax - row[i]) * BIN_INVW);
        bin = (bin > 255) ? 255 : bin;
        atomicAdd(&hist[255 - bin], 1u);
    }
    __syncthreads();
    select_bin(hist, TOPK, &s_bin, &s_k, lane, wid);
    __syncthreads();
    const int rb = 255 - s_bin;          // real (value) bin of the k-th largest
    const int kk = s_k;
    __syncthreads();

    // ---- scan 3: compact candidates from the chosen bucket ----
    for (int i = tid; i < LK; i += 256) {
        int bin = (int)((rowmax - row[i]) * BIN_INVW);
        bin = (bin > 255) ? 255 : bin;
        if (bin == rb) {
            int idx = atomicAdd(&s_cnt, 1);
            if (idx < CAND_CAP) cand[idx] = row[i];
        }
    }
    __syncthreads();
    const int ncand = s_cnt;
    const bool uselist = (rb != 255) && (ncand <= CAND_CAP);
    __syncthreads();

    // ---- exact k-th among candidates (tiny) or full row (fallback) ----
    float tau;
    if (uselist)
        tau = radix_select_dev(cand, ncand, kk, hist, &s_bin, &s_k, tid, lane, wid);
    else
        tau = radix_select_dev(row, LK, TOPK, hist, &s_bin, &s_k, tid, lane, wid);

    // ---- scan 4: unnormalized exp (fp16 hi/lo, vectorized) + sum ----
    float ssum = 0.f;
    for (int i = tid; i < LK / 4; i += 256) {
        float4 v = ((const float4*)row)[i];
        float p0 = (v.x >= tau) ? __expf((v.x - rowmax) * SM_SCALE) : 0.f;
        float p1 = (v.y >= tau) ? __expf((v.y - rowmax) * SM_SCALE) : 0.f;
        float p2 = (v.z >= tau) ? __expf((v.z - rowmax) * SM_SCALE) : 0.f;
        float p3 = (v.w >= tau) ? __expf((v.w - rowmax) * SM_SCALE) : 0.f;
        ssum += (p0 + p1) + (p2 + p3);
        __half h0 = __float2half_rn(p0), h1 = __float2half_rn(p1);
        __half h2 = __float2half_rn(p2), h3 = __float2half_rn(p3);
        __half l0 = __float2half_rn(p0 - __half2float(h0));
        __half l1 = __float2half_rn(p1 - __half2float(h1));
        __half l2 = __float2half_rn(p2 - __half2float(h2));
        __half l3 = __float2half_rn(p3 - __half2float(h3));
        uint2 hv, lv;
        hv.x = (uint32_t)__half_as_ushort(h0) | ((uint32_t)__half_as_ushort(h1) << 16);
        hv.y = (uint32_t)__half_as_ushort(h2) | ((uint32_t)__half_as_ushort(h3) << 16);
        lv.x = (uint32_t)__half_as_ushort(l0) | ((uint32_t)__half_as_ushort(l1) << 16);
        lv.y = (uint32_t)__half_as_ushort(l2) | ((uint32_t)__half_as_ushort(l3) << 16);
        ((uint2*)PhR)[i] = hv;
        ((uint2*)PlR)[i] = lv;
    }
#pragma unroll
    for (int o = 16; o > 0; o >>= 1) ssum += __shfl_xor_sync(0xFFFFFFFFu, ssum, o);
    if (lane == 0) redf[wid] = ssum;
    __syncthreads();
    if (tid == 0) {
        float t = 0.f;
#pragma unroll
        for (int i = 0; i < 8; i++) t += redf[i];
        g_rowinv[blockIdx.x] = 1.0f / t;
    }
}

// ---------------------------------------------------------------------------
extern "C" void kernel_launch(void* const* d_in, const int* in_sizes, int n_in,
                              void* d_out, int out_size)
{
    const float* Q = (const float*)d_in[0];
    const float* K = (const float*)d_in[1];
    const float* V = (const float*)d_in[2];
    float* O = (float*)d_out;

    cudaFuncSetAttribute(hmma_gemm, cudaFuncAttributeMaxDynamicSharedMemorySize, GEMM_SMEM);

    void *pQh, *pQl, *pKh, *pKl, *pVth, *pVtl, *pPh, *pPl, *pS, *pRI;
    cudaGetSymbolAddress(&pQh, g_Qh);   cudaGetSymbolAddress(&pQl, g_Ql);
    cudaGetSymbolAddress(&pKh, g_Kh);   cudaGetSymbolAddress(&pKl, g_Kl);
    cudaGetSymbolAddress(&pVth, g_Vth); cudaGetSymbolAddress(&pVtl, g_Vtl);
    cudaGetSymbolAddress(&pPh, g_Ph);   cudaGetSymbolAddress(&pPl, g_Pl);
    cudaGetSymbolAddress(&pS, g_scores);
    cudaGetSymbolAddress(&pRI, g_rowinv);

    const int n8 = (BB * LQ * DD) / 8;

    split_kernel<<<(n8 + 255) / 256, 256>>>((const float4*)Q,
        (__half*)pQh, (__half*)pQl, n8);
    split_kernel<<<(n8 + 255) / 256, 256>>>((const float4*)K,
        (__half*)pKh, (__half*)pKl, n8);

    vt_split<<<dim3(LK / 64, DD / 32, BB), 256>>>(V);

    // scores = Q @ K^T (UNSCALED; scale applied in softmax — selection is monotone)
    hmma_gemm<<<dim3(LK / 128, LQ / 128, BB), 256, GEMM_SMEM>>>(
        (const __half*)pQh, (const __half*)pQl, DD, (long)LQ * DD,
        (const __half*)pKh, (const __half*)pKl, DD, (long)LK * DD,
        (float*)pS, LK, (long)LQ * LK, DD, nullptr);

    topk_softmax<<<BB * LQ, 256>>>();

    // O = diag(1/Z) * (P_unnorm @ V)   (V pre-transposed to [b,d,k])
    hmma_gemm<<<dim3(DD / 128, LQ / 128, BB), 256, GEMM_SMEM>>>(
        (const __half*)pPh, (const __half*)pPl, LK, (long)LQ * LK,
        (const __half*)pVth, (const __half*)pVtl, LK, (long)DD * LK,
        O, DD, (long)LQ * DD, LK, (const float*)pRI);
}

// round 12
// speedup vs baseline: 1.5091x; 1.1454x over previous
#include <cuda_runtime.h>
#include <cuda_fp16.h>
#include <cstdint>

#define BB 16
#define LQ 2048
#define LK 2048
#define DD 512
#define TOPK 512

// ---------------------------------------------------------------------------
// Device-global scratch (no allocations allowed)
// ---------------------------------------------------------------------------
__device__ float  g_scores[(size_t)BB * LQ * LK];                 // 268 MB (unscaled)
__device__ float  g_rowinv[(size_t)BB * LQ];                      // per-row 1/Z
__device__ __half g_Qh[(size_t)BB * LQ * DD];
__device__ __half g_Ql[(size_t)BB * LQ * DD];
__device__ __half g_Kh[(size_t)BB * LK * DD];
__device__ __half g_Kl[(size_t)BB * LK * DD];
__device__ __half g_Vth[(size_t)BB * DD * LK];                    // V^T [b,d,k]
__device__ __half g_Vtl[(size_t)BB * DD * LK];
__device__ __half g_Ph[(size_t)BB * LQ * LK];                     // unnormalized exp (hi only)

// ---------------------------------------------------------------------------
// PTX helpers
// ---------------------------------------------------------------------------
__device__ __forceinline__ uint32_t smem_u32(const void* p) {
    uint32_t a;
    asm("{ .reg .u64 t; cvta.to.shared.u64 t, %1; cvt.u32.u64 %0, t; }" : "=r"(a) : "l"(p));
    return a;
}
__device__ __forceinline__ void cp16(uint32_t s, const void* g) {
    asm volatile("cp.async.cg.shared.global [%0], [%1], 16;" :: "r"(s), "l"(g));
}
__device__ __forceinline__ void cp_commit() { asm volatile("cp.async.commit_group;" ::: "memory"); }
__device__ __forceinline__ void cp_wait0()  { asm volatile("cp.async.wait_group 0;" ::: "memory"); }
__device__ __forceinline__ void cp_wait1()  { asm volatile("cp.async.wait_group 1;" ::: "memory"); }
__device__ __forceinline__ void cp_wait2()  { asm volatile("cp.async.wait_group 2;" ::: "memory"); }

__device__ __forceinline__ void ldsm4(uint32_t* r, uint32_t addr) {
    asm volatile("ldmatrix.sync.aligned.m8n8.x4.shared.b16 {%0,%1,%2,%3}, [%4];"
                 : "=r"(r[0]), "=r"(r[1]), "=r"(r[2]), "=r"(r[3]) : "r"(addr));
}
__device__ __forceinline__ void mma_f16(float* c, const uint32_t* a, const uint32_t* b) {
    asm volatile("mma.sync.aligned.m16n8k16.row.col.f32.f16.f16.f32 "
                 "{%0,%1,%2,%3}, {%4,%5,%6,%7}, {%8,%9}, {%0,%1,%2,%3};"
                 : "+f"(c[0]), "+f"(c[1]), "+f"(c[2]), "+f"(c[3])
                 : "r"(a[0]), "r"(a[1]), "r"(a[2]), "r"(a[3]), "r"(b[0]), "r"(b[1]));
}

// ---------------------------------------------------------------------------
// HMMA GEMM (fp16 hi/lo).
// HAS_AL=true : 3 terms AhBh + AhBl + AlBh (QK path).
// HAS_AL=false: 2 terms AhBh + AhBl        (PV path; A = Ph only).
// Block tile 128x128, BK=32, 8 warps (64x32 warp tiles), 2 CTAs/SM,
// triple-buffered cp.async.
// ---------------------------------------------------------------------------
#define MAT_BYTES 8192
#define BUF_BYTES (4 * MAT_BYTES)       // 32 KB
#define NSTAGE 3
#define GEMM_SMEM (NSTAGE * BUF_BYTES)  // 96 KB

template <bool HAS_AL>
__device__ __forceinline__ void load_buf(uint32_t sbase,
    const __half* __restrict__ Ah, const __half* __restrict__ Al, long ldA,
    const __half* __restrict__ Bh, const __half* __restrict__ Bl, long ldB,
    int kk, int tid)
{
    const int r0 = tid >> 2;            // 0..63
    const int c  = tid & 3;
#pragma unroll
    for (int p = 0; p < 2; p++) {
        const int r = r0 + p * 64;
        const uint32_t soff = r * 64 + ((c ^ ((r >> 1) & 3)) << 4);
        const size_t goffA = (size_t)r * ldA + kk + c * 8;
        const size_t goffB = (size_t)r * ldB + kk + c * 8;
        cp16(sbase + soff, Ah + goffA);
        if (HAS_AL) cp16(sbase + MAT_BYTES + soff, Al + goffA);
        cp16(sbase + 2 * MAT_BYTES + soff, Bh + goffB);
        cp16(sbase + 3 * MAT_BYTES + soff, Bl + goffB);
    }
}

template <bool HAS_AL>
__global__ __launch_bounds__(256, 2)
void hmma_gemm(const __half* __restrict__ Ah, const __half* __restrict__ Al,
               long ldA, long strideA,
               const __half* __restrict__ Bh, const __half* __restrict__ Bl,
               long ldB, long strideB,
               float* __restrict__ C, long ldC, long strideC, int Ktot,
               const float* __restrict__ rowScale)
{
    extern __shared__ char smem[];
    const uint32_t sbase = smem_u32(smem);

    const int tid  = threadIdx.x;
    const int lane = tid & 31, warp = tid >> 5;
    const int wm = (warp >> 2) * 64;
    const int wn = (warp & 3) * 32;
    const int b  = blockIdx.z;
    const int n0 = blockIdx.x * 128, m0 = blockIdx.y * 128;

    const __half* pAh = Ah + (size_t)b * strideA + (size_t)m0 * ldA;
    const __half* pAl = HAS_AL ? (Al + (size_t)b * strideA + (size_t)m0 * ldA) : pAh;
    const __half* pBh = Bh + (size_t)b * strideB + (size_t)n0 * ldB;
    const __half* pBl = Bl + (size_t)b * strideB + (size_t)n0 * ldB;

    const int aRow = (lane & 7) | (((lane >> 3) & 1) << 3);
    const int aCk  = (lane >> 4) & 1;
    const int bRow = (lane & 7) | (((lane >> 4) & 1) << 3);
    const int bCk  = (lane >> 3) & 1;

    float acc[4][4][4];
#pragma unroll
    for (int i = 0; i < 4; i++)
#pragma unroll
        for (int j = 0; j < 4; j++)
#pragma unroll
            for (int t = 0; t < 4; t++) acc[i][j][t] = 0.f;

    const int nc = Ktot / 32;

    load_buf<HAS_AL>(sbase, pAh, pAl, ldA, pBh, pBl, ldB, 0, tid);
    cp_commit();
    if (nc > 1) {
        load_buf<HAS_AL>(sbase + BUF_BYTES, pAh, pAl, ldA, pBh, pBl, ldB, 32, tid);
        cp_commit();
    }

    int stage = 0;
    for (int c = 0; c < nc; c++) {
        if (c + 2 < nc) {
            int ls = stage + 2; if (ls >= NSTAGE) ls -= NSTAGE;
            load_buf<HAS_AL>(sbase + ls * BUF_BYTES, pAh, pAl, ldA, pBh, pBl, ldB,
                             (c + 2) * 32, tid);
            cp_commit();
            cp_wait2();
        } else if (c + 1 < nc) {
            cp_wait1();
        } else {
            cp_wait0();
        }
        __syncthreads();

        const uint32_t bb = sbase + stage * BUF_BYTES;
#pragma unroll
        for (int s = 0; s < 2; s++) {
            uint32_t bh[2][4], bl[2][4];
#pragma unroll
            for (int np = 0; np < 2; np++) {
                const int r = wn + np * 16 + bRow;
                const int ck = s * 2 + bCk;
                const uint32_t off = r * 64 + ((ck ^ ((r >> 1) & 3)) << 4);
                ldsm4(bh[np], bb + 2 * MAT_BYTES + off);
                ldsm4(bl[np], bb + 3 * MAT_BYTES + off);
            }
#pragma unroll
            for (int mh = 0; mh < 2; mh++) {
                uint32_t ah[2][4], al[2][4];
#pragma unroll
                for (int mi = 0; mi < 2; mi++) {
                    const int r = wm + mh * 32 + mi * 16 + aRow;
                    const int ck = s * 2 + aCk;
                    const uint32_t off = r * 64 + ((ck ^ ((r >> 1) & 3)) << 4);
                    ldsm4(ah[mi], bb + off);
                    if (HAS_AL) ldsm4(al[mi], bb + MAT_BYTES + off);
                }
#pragma unroll
                for (int mi = 0; mi < 2; mi++)
#pragma unroll
                    for (int nj = 0; nj < 4; nj++)
                        mma_f16(acc[mh * 2 + mi][nj], ah[mi], &bh[nj >> 1][(nj & 1) * 2]);
#pragma unroll
                for (int mi = 0; mi < 2; mi++)
#pragma unroll
                    for (int nj = 0; nj < 4; nj++)
                        mma_f16(acc[mh * 2 + mi][nj], ah[mi], &bl[nj >> 1][(nj & 1) * 2]);
                if (HAS_AL) {
#pragma unroll
                    for (int mi = 0; mi < 2; mi++)
#pragma unroll
                        for (int nj = 0; nj < 4; nj++)
                            mma_f16(acc[mh * 2 + mi][nj], al[mi], &bh[nj >> 1][(nj & 1) * 2]);
                }
            }
        }
        __syncthreads();
        if (++stage == NSTAGE) stage = 0;
    }

    const int g = lane >> 2, tg = lane & 3;
    float* Cb = C + (size_t)b * strideC;
    const float* rs = rowScale ? rowScale + (size_t)b * LQ : nullptr;
#pragma unroll
    for (int mi = 0; mi < 4; mi++) {
        const int row = m0 + wm + mi * 16 + g;
        const float sA = rs ? rs[row]     : 1.f;
        const float sB = rs ? rs[row + 8] : 1.f;
#pragma unroll
        for (int nj = 0; nj < 4; nj++) {
            const int col = n0 + wn + nj * 8 + tg * 2;
            *(float2*)(Cb + (size_t)row * ldC + col) =
                make_float2(acc[mi][nj][0] * sA, acc[mi][nj][1] * sA);
            *(float2*)(Cb + (size_t)(row + 8) * ldC + col) =
                make_float2(acc[mi][nj][2] * sB, acc[mi][nj][3] * sB);
        }
    }
}

// ---------------------------------------------------------------------------
// fp32 -> (hi, lo) fp16 split, 8 elems/thread, uint4 stores
// ---------------------------------------------------------------------------
__global__ void split_kernel(const float4* __restrict__ in,
                             __half* __restrict__ hi,
                             __half* __restrict__ lo, int n8)
{
    int i = blockIdx.x * blockDim.x + threadIdx.x;
    if (i >= n8) return;
    float4 v0 = in[2 * i], v1 = in[2 * i + 1];
    float x[8] = { v0.x, v0.y, v0.z, v0.w, v1.x, v1.y, v1.z, v1.w };
    uint32_t hw[4], lw[4];
#pragma unroll
    for (int j = 0; j < 4; j++) {
        __half ha = __float2half_rn(x[2 * j]);
        __half hb = __float2half_rn(x[2 * j + 1]);
        __half la = __float2half_rn(x[2 * j] - __half2float(ha));
        __half lb = __float2half_rn(x[2 * j + 1] - __half2float(hb));
        hw[j] = (uint32_t)__half_as_ushort(ha) | ((uint32_t)__half_as_ushort(hb) << 16);
        lw[j] = (uint32_t)__half_as_ushort(la) | ((uint32_t)__half_as_ushort(lb) << 16);
    }
    *(uint4*)(hi + 8 * (size_t)i) = make_uint4(hw[0], hw[1], hw[2], hw[3]);
    *(uint4*)(lo + 8 * (size_t)i) = make_uint4(lw[0], lw[1], lw[2], lw[3]);
}

// ---------------------------------------------------------------------------
// Transpose V [b,k,d] -> Vt [b,d,k], split hi/lo fp16. 64k x 32d tiles,
// packed uint4 (8-half) stores.
// ---------------------------------------------------------------------------
__global__ __launch_bounds__(256)
void vt_split(const float* __restrict__ V)
{
    __shared__ float tile[64][33];
    const int b = blockIdx.z;
    const int k0 = blockIdx.x * 64, d0 = blockIdx.y * 32;
    const int tid = threadIdx.x;
    const float* Vb = V + (size_t)b * LK * DD;

    const int lx = tid & 31, lr = tid >> 5;
#pragma unroll
    for (int r = lr; r < 64; r += 8)
        tile[r][lx] = Vb[(size_t)(k0 + r) * DD + d0 + lx];
    __syncthreads();

    const int rr = tid >> 3;            // d-row 0..31
    const int kc = (tid & 7) * 8;       // k-chunk
    uint32_t hw[4], lw[4];
#pragma unroll
    for (int j = 0; j < 4; j++) {
        float xa = tile[kc + 2 * j][rr];
        float xb = tile[kc + 2 * j + 1][rr];
        __half ha = __float2half_rn(xa), hb = __float2half_rn(xb);
        __half la = __float2half_rn(xa - __half2float(ha));
        __half lb = __float2half_rn(xb - __half2float(hb));
        hw[j] = (uint32_t)__half_as_ushort(ha) | ((uint32_t)__half_as_ushort(hb) << 16);
        lw[j] = (uint32_t)__half_as_ushort(la) | ((uint32_t)__half_as_ushort(lb) << 16);
    }
    size_t o = (size_t)b * DD * LK + (size_t)(d0 + rr) * LK + k0 + kc;
    *(uint4*)(g_Vth + o) = make_uint4(hw[0], hw[1], hw[2], hw[3]);
    *(uint4*)(g_Vtl + o) = make_uint4(lw[0], lw[1], lw[2], lw[3]);
}

// ---------------------------------------------------------------------------
// Top-k + sparse softmax (linear-bucket select + exact radix on candidates).
// Writes UNNORMALIZED exp to Ph only (fp16 hi), 1/Z to g_rowinv.
// ---------------------------------------------------------------------------
__device__ __forceinline__ unsigned fkey(float x) {
    unsigned u = __float_as_uint(x);
    return u ^ ((u >> 31) ? 0xFFFFFFFFu : 0x80000000u);
}
__device__ __forceinline__ float fkey_inv(unsigned u) {
    unsigned bits = (u >> 31) ? (u ^ 0x80000000u) : ~u;
    return __uint_as_float(bits);
}

#define CAND_CAP 1024
#define SM_SCALE 0.04419417382415922f   // 1/sqrt(512)
#define BIN_INVW 2.0f                   // linear bin width 0.5, window 128

__device__ __forceinline__ void select_bin(const unsigned* hist, int k,
                                           int* ps_bin, int* ps_k,
                                           int lane, int wid)
{
    if (wid == 0) {
        unsigned h[8], tot = 0;
#pragma unroll
        for (int j = 0; j < 8; j++) { h[j] = hist[lane * 8 + j]; tot += h[j]; }
        unsigned suf = tot;
#pragma unroll
        for (int o = 1; o < 32; o <<= 1) {
            unsigned v = __shfl_down_sync(0xFFFFFFFFu, suf, o);
            if (lane + o < 32) suf += v;
        }
        unsigned run = suf - tot;
        for (int j = 7; j >= 0; j--) {
            unsigned cge = run + h[j];
            if (cge >= (unsigned)k && run < (unsigned)k) {
                *ps_bin = lane * 8 + j;
                *ps_k = k - (int)run;
            }
            run = cge;
        }
    }
}

__device__ __forceinline__ float radix_select_dev(const float* arr, int n, int k,
                                                  unsigned* hist, int* ps_bin, int* ps_k,
                                                  int tid, int lane, int wid)
{
    unsigned prefix = 0;
#pragma unroll
    for (int pass = 0; pass < 4; pass++) {
        const int shift = 24 - pass * 8;
        const unsigned mask = pass ? (0xFFFFFFFFu << (32 - 8 * pass)) : 0u;
        if (tid < 256) hist[tid] = 0;
        __syncthreads();
        for (int i = tid; i < n; i += 256) {
            unsigned u = fkey(arr[i]);
            if ((u & mask) == prefix)
                atomicAdd(&hist[(u >> shift) & 0xFF], 1u);
        }
        __syncthreads();
        select_bin(hist, k, ps_bin, ps_k, lane, wid);
        __syncthreads();
        prefix |= ((unsigned)*ps_bin) << shift;
        k = *ps_k;
        __syncthreads();
    }
    return fkey_inv(prefix);
}

__global__ __launch_bounds__(256)
void topk_softmax(void)
{
    __shared__ float row[LK];            // 8 KB
    __shared__ float cand[CAND_CAP];     // 4 KB
    __shared__ unsigned hist[256];
    __shared__ float redf[8];
    __shared__ float s_bcast;
    __shared__ int s_bin, s_k, s_cnt;

    const int tid = threadIdx.x;
    const int lane = tid & 31, wid = tid >> 5;
    const float* Srow = g_scores + (size_t)blockIdx.x * LK;
    __half* PhR = g_Ph + (size_t)blockIdx.x * LK;

    if (tid == 0) s_cnt = 0;

    // ---- scan 1: load + rowmax ----
    float m = -3.4e38f;
    for (int i = tid; i < LK / 4; i += 256) {
        float4 v = ((const float4*)Srow)[i];
        ((float4*)row)[i] = v;
        m = fmaxf(fmaxf(m, v.x), fmaxf(v.y, v.z));
        m = fmaxf(m, v.w);
    }
#pragma unroll
    for (int o = 16; o > 0; o >>= 1) m = fmaxf(m, __shfl_xor_sync(0xFFFFFFFFu, m, o));
    if (lane == 0) redf[wid] = m;
    __syncthreads();
    if (tid == 0) {
        float mm = redf[0];
#pragma unroll
        for (int i = 1; i < 8; i++) mm = fmaxf(mm, redf[i]);
        s_bcast = mm;
    }
    if (tid < 256) hist[tid] = 0;
    __syncthreads();
    const float rowmax = s_bcast;

    // ---- scan 2: linear-bucket histogram (flipped so high bins = top) ----
    for (int i = tid; i < LK; i += 256) {
        int bin = (int)((rowmax - row[i]) * BIN_INVW);
        bin = (bin > 255) ? 255 : bin;
        atomicAdd(&hist[255 - bin], 1u);
    }
    __syncthreads();
    select_bin(hist, TOPK, &s_bin, &s_k, lane, wid);
    __syncthreads();
    const int rb = 255 - s_bin;
    const int kk = s_k;
    __syncthreads();

    // ---- scan 3: compact candidates from the chosen bucket ----
    for (int i = tid; i < LK; i += 256) {
        int bin = (int)((rowmax - row[i]) * BIN_INVW);
        bin = (bin > 255) ? 255 : bin;
        if (bin == rb) {
            int idx = atomicAdd(&s_cnt, 1);
            if (idx < CAND_CAP) cand[idx] = row[i];
        }
    }
    __syncthreads();
    const int ncand = s_cnt;
    const bool uselist = (rb != 255) && (ncand <= CAND_CAP);
    __syncthreads();

    float tau;
    if (uselist)
        tau = radix_select_dev(cand, ncand, kk, hist, &s_bin, &s_k, tid, lane, wid);
    else
        tau = radix_select_dev(row, LK, TOPK, hist, &s_bin, &s_k, tid, lane, wid);

    // ---- scan 4: unnormalized exp (fp16 hi only, vectorized) + sum ----
    float ssum = 0.f;
    for (int i = tid; i < LK / 4; i += 256) {
        float4 v = ((const float4*)row)[i];
        float p0 = (v.x >= tau) ? __expf((v.x - rowmax) * SM_SCALE) : 0.f;
        float p1 = (v.y >= tau) ? __expf((v.y - rowmax) * SM_SCALE) : 0.f;
        float p2 = (v.z >= tau) ? __expf((v.z - rowmax) * SM_SCALE) : 0.f;
        float p3 = (v.w >= tau) ? __expf((v.w - rowmax) * SM_SCALE) : 0.f;
        ssum += (p0 + p1) + (p2 + p3);
        uint2 hv;
        hv.x = (uint32_t)__half_as_ushort(__float2half_rn(p0))
             | ((uint32_t)__half_as_ushort(__float2half_rn(p1)) << 16);
        hv.y = (uint32_t)__half_as_ushort(__float2half_rn(p2))
             | ((uint32_t)__half_as_ushort(__float2half_rn(p3)) << 16);
        ((uint2*)PhR)[i] = hv;
    }
#pragma unroll
    for (int o = 16; o > 0; o >>= 1) ssum += __shfl_xor_sync(0xFFFFFFFFu, ssum, o);
    if (lane == 0) redf[wid] = ssum;
    __syncthreads();
    if (tid == 0) {
        float t = 0.f;
#pragma unroll
        for (int i = 0; i < 8; i++) t += redf[i];
        g_rowinv[blockIdx.x] = 1.0f / t;
    }
}

// ---------------------------------------------------------------------------
extern "C" void kernel_launch(void* const* d_in, const int* in_sizes, int n_in,
                              void* d_out, int out_size)
{
    const float* Q = (const float*)d_in[0];
    const float* K = (const float*)d_in[1];
    const float* V = (const float*)d_in[2];
    float* O = (float*)d_out;

    cudaFuncSetAttribute(hmma_gemm<true>,  cudaFuncAttributeMaxDynamicSharedMemorySize, GEMM_SMEM);
    cudaFuncSetAttribute(hmma_gemm<false>, cudaFuncAttributeMaxDynamicSharedMemorySize, GEMM_SMEM);

    void *pQh, *pQl, *pKh, *pKl, *pVth, *pVtl, *pPh, *pS, *pRI;
    cudaGetSymbolAddress(&pQh, g_Qh);   cudaGetSymbolAddress(&pQl, g_Ql);
    cudaGetSymbolAddress(&pKh, g_Kh);   cudaGetSymbolAddress(&pKl, g_Kl);
    cudaGetSymbolAddress(&pVth, g_Vth); cudaGetSymbolAddress(&pVtl, g_Vtl);
    cudaGetSymbolAddress(&pPh, g_Ph);
    cudaGetSymbolAddress(&pS, g_scores);
    cudaGetSymbolAddress(&pRI, g_rowinv);

    const int n8 = (BB * LQ * DD) / 8;

    split_kernel<<<(n8 + 255) / 256, 256>>>((const float4*)Q,
        (__half*)pQh, (__half*)pQl, n8);
    split_kernel<<<(n8 + 255) / 256, 256>>>((const float4*)K,
        (__half*)pKh, (__half*)pKl, n8);

    vt_split<<<dim3(LK / 64, DD / 32, BB), 256>>>(V);

    // scores = Q @ K^T (3-term; unscaled — scale applied in softmax)
    hmma_gemm<true><<<dim3(LK / 128, LQ / 128, BB), 256, GEMM_SMEM>>>(
        (const __half*)pQh, (const __half*)pQl, DD, (long)LQ * DD,
        (const __half*)pKh, (const __half*)pKl, DD, (long)LK * DD,
        (float*)pS, LK, (long)LQ * LK, DD, nullptr);

    topk_softmax<<<BB * LQ, 256>>>();

    // O = diag(1/Z) * (Ph @ V)  — 2-term PV (Ph·Vh + Ph·Vl)
    hmma_gemm<false><<<dim3(DD / 128, LQ / 128, BB), 256, GEMM_SMEM>>>(
        (const __half*)pPh, nullptr, LK, (long)LQ * LK,
        (const __half*)pVth, (const __half*)pVtl, LK, (long)DD * LK,
        O, DD, (long)LQ * DD, LK, (const float*)pRI);
}